// round 12
// baseline (speedup 1.0000x reference)
#include <cuda_runtime.h>
#include <cuda_fp16.h>
#include <cstdint>

#define M_    8
#define K_    256
#define DG_   128
#define D_    1024
#define HW_   1024
#define NPIX_ 32768
#define QUANT_ELEMS 33554432
#define CODE_ELEMS  262144
#define GAP_THRESH 5e-3f
#define REF_WIN    8e-3f
#define CAP_       32768

__device__ unsigned short g_Eh[M_ * K_ * DG_];   // E [m][k][d] fp16
__device__ unsigned short g_Vh[M_ * DG_ * K_];   // Vt [m][d][k] fp16
__device__ float g_KPH[M_ * K_ * DG_];
__device__ float g_KPL[M_ * K_ * DG_];
__device__ int   g_count;
__device__ int   g_list[CAP_];

__device__ __forceinline__ uint32_t smem_to_u32(const void* p) {
    uint32_t a;
    asm("{ .reg .u64 t; cvta.to.shared.u64 t, %1; cvt.u32.u64 %0, t; }" : "=r"(a) : "l"(p));
    return a;
}
__device__ __forceinline__ void ldsm4(uint32_t* r, uint32_t addr) {
    asm volatile("ldmatrix.sync.aligned.m8n8.x4.shared.b16 {%0,%1,%2,%3}, [%4];"
        : "=r"(r[0]), "=r"(r[1]), "=r"(r[2]), "=r"(r[3]) : "r"(addr));
}
__device__ __forceinline__ void mma_f16(float* d, const uint32_t* a, const uint32_t* b) {
    asm volatile("mma.sync.aligned.m16n8k16.row.col.f32.f16.f16.f32 "
        "{%0,%1,%2,%3}, {%4,%5,%6,%7}, {%8,%9}, {%0,%1,%2,%3};"
        : "+f"(d[0]), "+f"(d[1]), "+f"(d[2]), "+f"(d[3])
        : "r"(a[0]), "r"(a[1]), "r"(a[2]), "r"(a[3]), "r"(b[0]), "r"(b[1]));
}

struct dd { float h, l; };
__device__ __forceinline__ dd two_sum(float a, float b) {
    float s = __fadd_rn(a, b), bb = __fsub_rn(s, a);
    float e = __fadd_rn(__fsub_rn(a, __fsub_rn(s, bb)), __fsub_rn(b, bb));
    dd r; r.h = s; r.l = e; return r;
}
__device__ __forceinline__ dd two_prod(float a, float b) {
    float p = __fmul_rn(a, b), e = __fmaf_rn(a, b, -p);
    dd r; r.h = p; r.l = e; return r;
}
__device__ __forceinline__ dd dd_add(dd x, dd y) {
    dd s = two_sum(x.h, y.h);
    float lo = __fadd_rn(__fadd_rn(x.l, y.l), s.l);
    float hi = __fadd_rn(s.h, lo);
    float l = __fadd_rn(__fsub_rn(s.h, hi), lo);
    dd r; r.h = hi; r.l = l; return r;
}
__device__ __forceinline__ dd dd_fma(dd a, float x, float y) { return dd_add(a, two_prod(x, y)); }
__device__ __forceinline__ dd dd_mul(dd x, dd y) {
    dd p = two_prod(x.h, y.h);
    float t = __fmaf_rn(x.h, y.l, p.l); t = __fmaf_rn(x.l, y.h, t);
    float hi = __fadd_rn(p.h, t), l = __fadd_rn(__fsub_rn(p.h, hi), t);
    dd r; r.h = hi; r.l = l; return r;
}
__device__ __forceinline__ float neglog_acc(float u) {
    float t = __fsub_rn(u, 1.0f);
    float p = fmaf(t, 0.142857143f, -0.166666667f);
    p = fmaf(t, p, 0.2f); p = fmaf(t, p, -0.25f);
    p = fmaf(t, p, 0.333333333f); p = fmaf(t, p, -0.5f); p = fmaf(t, p, 1.0f);
    return (u > 0.75f) ? -(t * p) : -__logf(u);
}

// ---------------- precompute: kproj(dd), Vt/E fp16 ----------------
#define P_CB 0
#define P_KP 1024
#define P_WK 2048
#define P_WV (2048 + 4224)
#define P_WQ 2048
#define P_FLOATS (2048 + 4224 + 4224)

__global__ void __launch_bounds__(256)
precompute_kernel(const float* __restrict__ codebook, const float* __restrict__ wq,
                  const float* __restrict__ wk, const float* __restrict__ wv) {
    __shared__ float sm[P_FLOATS];
    float *cbs = sm + P_CB, *kps = sm + P_KP, *wks = sm + P_WK, *wvs = sm + P_WV, *wqs = sm + P_WQ;
    const int m = blockIdx.y, k0 = blockIdx.x * 8, tid = threadIdx.x;
    const int c = tid & 127, khalf = tid >> 7;
    if (m == 0 && blockIdx.x == 0 && tid == 0) g_count = 0;
#pragma unroll
    for (int r = 0; r < 4; r++) {
        int idx = tid + 256 * r;
        cbs[idx] = codebook[((size_t)m * K_ + k0) * DG_ + idx];
    }
    dd sk[4]; float sv[4];
#pragma unroll
    for (int i = 0; i < 4; i++) { sk[i].h = sk[i].l = 0.f; sv[i] = 0.f; }
    const float* wkm = wk + (size_t)m * DG_ * DG_;
    const float* wvm = wv + (size_t)m * DG_ * DG_;
    for (int dc = 0; dc < DG_; dc += 32) {
        __syncthreads();
#pragma unroll
        for (int r = 0; r < 16; r++) {
            int idx = tid + 256 * r, cc = idx >> 5, j = idx & 31;
            wks[cc * 33 + j] = wkm[(size_t)cc * DG_ + dc + j];
            wvs[cc * 33 + j] = wvm[(size_t)cc * DG_ + dc + j];
        }
        __syncthreads();
#pragma unroll 4
        for (int j = 0; j < 32; j++) {
            float wkv = wks[c * 33 + j], wvv = wvs[c * 33 + j];
#pragma unroll
            for (int i = 0; i < 4; i++) {
                float cbv = cbs[(khalf * 4 + i) * DG_ + dc + j];
                sk[i] = dd_fma(sk[i], cbv, wkv);
                sv[i] = fmaf(cbv, wvv, sv[i]);
            }
        }
    }
#pragma unroll
    for (int i = 0; i < 4; i++) {
        int kk = k0 + khalf * 4 + i;
        size_t gb = ((size_t)m * K_ + kk) * DG_ + c;
        g_KPH[gb] = sk[i].h; g_KPL[gb] = sk[i].l;
        g_Vh[((size_t)m * DG_ + c) * K_ + kk] = __half_as_ushort(__float2half_rn(sv[i]));
        kps[(khalf * 4 + i) * DG_ + c] = sk[i].h;
    }
    const int d = c;
    float ea[4] = {0.f, 0.f, 0.f, 0.f};
    const float* wqm = wq + (size_t)m * DG_ * DG_;
    for (int c0 = 0; c0 < DG_; c0 += 32) {
        __syncthreads();
#pragma unroll
        for (int r = 0; r < 16; r++) {
            int idx = tid + 256 * r;
            wqs[idx] = wqm[(size_t)c0 * DG_ + idx];
        }
        __syncthreads();
#pragma unroll 4
        for (int cc = 0; cc < 32; cc++) {
            float wv_ = wqs[cc * DG_ + d];
#pragma unroll
            for (int i = 0; i < 4; i++)
                ea[i] = fmaf(kps[(khalf * 4 + i) * DG_ + c0 + cc], wv_, ea[i]);
        }
    }
#pragma unroll
    for (int i = 0; i < 4; i++)
        g_Eh[((size_t)m * K_ + k0 + khalf * 4 + i) * DG_ + d] =
            __half_as_ushort(__float2half_rn(ea[i]));
}

// ---------------- main mma.sync kernel: 64 pix x fixed m, 2 CTAs/SM ----------------
// smem map (bytes):
//  [0..4096)         small buffers
//  [4096..37888)     S (normalized) fp16 [64][528B rows]
//  [37888..71680)    stage: A[64][80]=5120 + E[256][80]=20480 (25600)
//                     / V[128][144]=18432 / qbuf[64][132]f32=33792
#define SM_B1S  0
#define SM_B2S  512
#define SM_I1S  1024
#define SM_SUMS 1536
#define SM_RI   2048
#define SM_SSH  4096
#define SM_STG  37888
#define SM_AH   (SM_STG)
#define SM_EH   (SM_STG + 5120)
#define SM_VH   (SM_STG)
#define SM_QB   (SM_STG)
#define SMEM_TOTAL (37888 + 33792)   // 71680

#define UPD(b1, b2, i1, v, k) do { \
    if ((v) > (b1)) { b2 = b1; b1 = (v); i1 = (k); } \
    else if ((v) > (b2)) b2 = (v); } while (0)

// d-chunk = 32 (4 iterations)
#define LOAD_A(c4) do { _Pragma("unroll") \
    for (int j = 0; j < 4; j++) { \
        int dp = (tid >> 6) + 4 * j, pix = tid & 63; \
        pfA[2 * j]     = latb[(size_t)(32 * (c4) + 2 * dp) * HW_ + pix]; \
        pfA[2 * j + 1] = latb[(size_t)(32 * (c4) + 2 * dp + 1) * HW_ + pix]; \
    } } while (0)
#define LOAD_E(c4) do { _Pragma("unroll") \
    for (int j = 0; j < 4; j++) pfE[j] = ebH[(size_t)tid * 16 + (c4) * 4 + j]; \
    } while (0)
#define STORE_AE() do { _Pragma("unroll") \
    for (int j = 0; j < 4; j++) { \
        int dp = (tid >> 6) + 4 * j, pix = tid & 63; \
        unsigned short h0 = __half_as_ushort(__float2half_rn(pfA[2 * j])); \
        unsigned short h1 = __half_as_ushort(__float2half_rn(pfA[2 * j + 1])); \
        *(uint32_t*)(smem + SM_AH + pix * 80 + dp * 4) = ((uint32_t)h1 << 16) | h0; \
        *(uint4*)(smem + SM_EH + tid * 80 + j * 16) = pfE[j]; \
    } } while (0)
// k-chunk = 64 (4 iterations)
#define LOAD_V(it) do { _Pragma("unroll") \
    for (int jj = 0; jj < 4; jj++) { \
        int q = tid + 256 * jj; \
        pfV[jj] = vtH[(size_t)(q >> 3) * 32 + (it) * 8 + (q & 7)]; \
    } } while (0)
#define STORE_V() do { _Pragma("unroll") \
    for (int jj = 0; jj < 4; jj++) { \
        int q = tid + 256 * jj, dR = q >> 3, kc = q & 7; \
        *(uint4*)(smem + SM_VH + dR * 144 + kc * 16) = pfV[jj]; \
    } } while (0)

__global__ void __launch_bounds__(256, 2)
main_kernel(const float* __restrict__ latent, const float* __restrict__ unif,
            float* __restrict__ quant_out, float* __restrict__ code_out,
            float* __restrict__ logit_out) {
    extern __shared__ char smem[];
    const uint32_t sb = smem_to_u32(smem);
    const int m = blockIdx.y, p0 = blockIdx.x * 64;
    const int n = p0 >> 10, s0 = p0 & 1023;
    const int tid = threadIdx.x, w = tid >> 5, lane = tid & 31;
    const int wp = w >> 1, wk = w & 1;
    const int gid = lane >> 2, tig = lane & 3;
    const int li = lane & 7, lg = lane >> 3;

    float* b1s = (float*)(smem + SM_B1S);
    float* b2s = (float*)(smem + SM_B2S);
    int*   i1s = (int*)(smem + SM_I1S);
    float* sums = (float*)(smem + SM_SUMS);
    float* rinv = (float*)(smem + SM_RI);
    float* qbuf = (float*)(smem + SM_QB);

    const int a_row = wp * 16 + ((lg & 1) << 3) + li;
    const int a_col = ((lg >> 1) << 3);
    const int b_row = ((lg >> 1) << 3) + li;
    const int b_col = ((lg & 1) << 3);
    const uint32_t aAh = sb + SM_AH + a_row * 80 + a_col * 2;
    const uint32_t aEh = sb + SM_EH + (wk * 128 + b_row) * 80 + b_col * 2;

    const float* latb = latent + ((size_t)n * D_ + (size_t)m * DG_) * HW_ + s0;
    const uint4* ebH = (const uint4*)(g_Eh + (size_t)m * K_ * DG_);
    const uint4* vtH = (const uint4*)(g_Vh + (size_t)m * DG_ * K_);

    // ================= GEMM1: logits[64 pix][256 k], d-chunks of 32 =================
    float acc[16][4];
#pragma unroll
    for (int i = 0; i < 16; i++)
#pragma unroll
        for (int j = 0; j < 4; j++) acc[i][j] = 0.f;

    float pfA[8];
    uint4 pfE[4];
    LOAD_A(0); LOAD_E(0);

    for (int c4 = 0; c4 < 4; c4++) {
        STORE_AE();
        __syncthreads();
        if (c4 < 3) { LOAD_A(c4 + 1); LOAD_E(c4 + 1); }
#pragma unroll
        for (int s = 0; s < 2; s++) {
            uint32_t ah[4];
            ldsm4(ah, aAh + s * 32);
#pragma unroll
            for (int nf2 = 0; nf2 < 8; nf2++) {
                uint32_t bh[4];
                ldsm4(bh, aEh + nf2 * 1280 + s * 32);
                mma_f16(acc[2 * nf2], ah, bh);
                mma_f16(acc[2 * nf2 + 1], ah, bh + 2);
            }
        }
        __syncthreads();
    }

    // ================= Epilogue pass 1: logits out, top-2, e -> acc =================
    const int p_r = wp * 16 + gid;
    const size_t pgA = (size_t)(p0 + p_r), pgB = pgA + 8;
    float* lpA = logit_out + (pgA * M_ + m) * K_ + wk * 128 + 2 * tig;
    float* lpB = logit_out + (pgB * M_ + m) * K_ + wk * 128 + 2 * tig;
    const float* upA = unif + (pgA * M_ + m) * K_ + wk * 128 + 2 * tig;
    const float* upB = unif + (pgB * M_ + m) * K_ + wk * 128 + 2 * tig;

    float b1r[2] = {-3.4e38f, -3.4e38f}, b2r[2] = {-3.4e38f, -3.4e38f};
    int i1r[2] = {0, 0};
    float sumr[2] = {0.f, 0.f};

#pragma unroll
    for (int nf = 0; nf < 16; nf++) {
        int kk = wk * 128 + nf * 8 + 2 * tig;
        float l00 = acc[nf][0], l01 = acc[nf][1], l10 = acc[nf][2], l11 = acc[nf][3];
        *(float2*)(lpA + nf * 8) = make_float2(l00, l01);
        *(float2*)(lpB + nf * 8) = make_float2(l10, l11);
        float2 u0 = *(const float2*)(upA + nf * 8);
        float2 u1 = *(const float2*)(upB + nf * 8);
        UPD(b1r[0], b2r[0], i1r[0], l00, kk);
        UPD(b1r[0], b2r[0], i1r[0], l01, kk + 1);
        UPD(b1r[1], b2r[1], i1r[1], l10, kk);
        UPD(b1r[1], b2r[1], i1r[1], l11, kk + 1);
        float e00 = __fdividef(__expf(l00), neglog_acc(u0.x));
        float e01 = __fdividef(__expf(l01), neglog_acc(u0.y));
        float e10 = __fdividef(__expf(l10), neglog_acc(u1.x));
        float e11 = __fdividef(__expf(l11), neglog_acc(u1.y));
        sumr[0] += e00 + e01;
        sumr[1] += e10 + e11;
        acc[nf][0] = e00; acc[nf][1] = e01; acc[nf][2] = e10; acc[nf][3] = e11;
    }

    uint4 pfV[4];
    LOAD_V(0);

#pragma unroll
    for (int r = 0; r < 2; r++) {
#pragma unroll
        for (int o = 1; o <= 2; o <<= 1) {
            float ob1 = __shfl_xor_sync(0xFFFFFFFFu, b1r[r], o);
            int   oi1 = __shfl_xor_sync(0xFFFFFFFFu, i1r[r], o);
            float ob2 = __shfl_xor_sync(0xFFFFFFFFu, b2r[r], o);
            if (ob1 > b1r[r] || (ob1 == b1r[r] && oi1 < i1r[r])) {
                b2r[r] = fmaxf(b1r[r], ob2); b1r[r] = ob1; i1r[r] = oi1;
            } else b2r[r] = fmaxf(b2r[r], ob1);
            sumr[r] += __shfl_xor_sync(0xFFFFFFFFu, sumr[r], o);
        }
    }
    if (tig == 0) {
        b1s[wk * 64 + p_r] = b1r[0];  b1s[wk * 64 + p_r + 8] = b1r[1];
        b2s[wk * 64 + p_r] = b2r[0];  b2s[wk * 64 + p_r + 8] = b2r[1];
        i1s[wk * 64 + p_r] = i1r[0];  i1s[wk * 64 + p_r + 8] = i1r[1];
        sums[wk * 64 + p_r] = sumr[0]; sums[wk * 64 + p_r + 8] = sumr[1];
    }
    __syncthreads();

    if (tid < 64) {
        const int p = tid;
        const size_t pg = (size_t)(p0 + p);
        float a1 = b1s[p], a2 = b2s[p];           int ai = i1s[p];
        float c1 = b1s[64 + p], c2 = b2s[64 + p]; int ci = i1s[64 + p];
        float b1, b2; int i1;
        if (a1 >= c1) { b1 = a1; i1 = ai; b2 = fmaxf(a2, fmaxf(c1, c2)); }
        else          { b1 = c1; i1 = ci; b2 = fmaxf(c2, fmaxf(a1, a2)); }
        rinv[p] = 1.0f / (sums[p] + sums[64 + p]);
        code_out[pg * M_ + m] = (float)i1;
        if (b1 - b2 < GAP_THRESH) {
            int idx = atomicAdd(&g_count, 1);
            if (idx < CAP_) g_list[idx] = (int)(pg * M_ + m);
        }
    }
    __syncthreads();

    // ================= Epilogue pass 2: normalize S -> fp16 smem =================
    {
        const float riA = rinv[p_r], riB = rinv[p_r + 8];
#pragma unroll
        for (int nf = 0; nf < 16; nf++) {
            int kk = wk * 128 + nf * 8 + 2 * tig;
            unsigned short h00 = __half_as_ushort(__float2half_rn(acc[nf][0] * riA));
            unsigned short h01 = __half_as_ushort(__float2half_rn(acc[nf][1] * riA));
            unsigned short h10 = __half_as_ushort(__float2half_rn(acc[nf][2] * riB));
            unsigned short h11 = __half_as_ushort(__float2half_rn(acc[nf][3] * riB));
            *(uint32_t*)(smem + SM_SSH + p_r * 528 + kk * 2)       = ((uint32_t)h01 << 16) | h00;
            *(uint32_t*)(smem + SM_SSH + (p_r + 8) * 528 + kk * 2) = ((uint32_t)h11 << 16) | h10;
        }
    }

    // ================= GEMM2: quant[64 pix][128 d], k-chunks of 64 =================
    float acc2[8][4];
#pragma unroll
    for (int i = 0; i < 8; i++)
#pragma unroll
        for (int j = 0; j < 4; j++) acc2[i][j] = 0.f;

    const uint32_t aSh = sb + SM_SSH + a_row * 528 + a_col * 2;
    const uint32_t bvh = sb + SM_VH + (wk * 64 + b_row) * 144 + b_col * 2;

    for (int it = 0; it < 4; it++) {
        STORE_V();
        __syncthreads();
        if (it < 3) LOAD_V(it + 1);
#pragma unroll
        for (int s = 0; s < 4; s++) {
            const int k0 = it * 64 + s * 16;
            uint32_t sh[4];
            ldsm4(sh, aSh + k0 * 2);
#pragma unroll
            for (int nf2 = 0; nf2 < 4; nf2++) {
                uint32_t bh[4];
                ldsm4(bh, bvh + nf2 * 2304 + s * 32);
                mma_f16(acc2[2 * nf2], sh, bh);
                mma_f16(acc2[2 * nf2 + 1], sh, bh + 2);
            }
        }
        __syncthreads();
    }

#pragma unroll
    for (int nf = 0; nf < 8; nf++) {
        int d = wk * 64 + 8 * nf + 2 * tig;
        qbuf[p_r * 132 + d]       = acc2[nf][0];
        qbuf[p_r * 132 + d + 1]   = acc2[nf][1];
        qbuf[(p_r + 8) * 132 + d]     = acc2[nf][2];
        qbuf[(p_r + 8) * 132 + d + 1] = acc2[nf][3];
    }
    __syncthreads();
    {
        const int pix = tid & 63, dg2 = tid >> 6;
        float* qb = quant_out + ((size_t)n * D_ + (size_t)m * DG_) * HW_ + s0 + pix;
#pragma unroll
        for (int j = 0; j < 32; j++) {
            int d = dg2 * 32 + j;
            qb[(size_t)d * HW_] = qbuf[pix * 132 + d];
        }
    }
}

// ---------------- refine: dd-exact argmax for near-tie pixels ----------------
__global__ void __launch_bounds__(128)
refine_kernel(const float* __restrict__ latent, const float* __restrict__ wq,
              const float* __restrict__ logit_out, float* __restrict__ code_out) {
    __shared__ float qv_s[4][DG_], qh_s[4][DG_], ql_s[4][DG_];
    const int wid = threadIdx.x >> 5, lane = threadIdx.x & 31;
    const int gw = blockIdx.x * 4 + wid, tw = gridDim.x * 4;
    int cnt = g_count; if (cnt > CAP_) cnt = CAP_;
    for (int e = gw; e < cnt; e += tw) {
        int ent = g_list[e], m = ent & 7, pg = ent >> 3;
        int n = pg >> 10, s = pg & 1023;
        const float* latb = latent + ((size_t)n * D_ + (size_t)m * DG_) * HW_ + s;
        for (int d = lane; d < DG_; d += 32) qv_s[wid][d] = latb[(size_t)d * HW_];
        __syncwarp();
        const float* wqm = wq + (size_t)m * DG_ * DG_;
#pragma unroll
        for (int ci = 0; ci < 4; ci++) {
            int c = lane + 32 * ci;
            const float* wr = wqm + (size_t)c * DG_;
            dd a; a.h = a.l = 0.f;
            for (int d = 0; d < DG_; d++) a = dd_fma(a, qv_s[wid][d], wr[d]);
            qh_s[wid][c] = a.h; ql_s[wid][c] = a.l;
        }
        __syncwarp();
        const float* lo = logit_out + ((size_t)pg * M_ + m) * K_;
        float l[8], fm = -3.4e38f;
#pragma unroll
        for (int j = 0; j < 8; j++) { l[j] = lo[lane * 8 + j]; fm = fmaxf(fm, l[j]); }
#pragma unroll
        for (int o = 16; o > 0; o >>= 1) fm = fmaxf(fm, __shfl_xor_sync(0xFFFFFFFFu, fm, o));
        float thresh = fm - REF_WIN;
        double bestv = -1e300; int besti = 1 << 30;
        const float* kph = g_KPH + ((size_t)m * K_) * DG_;
        const float* kpl = g_KPL + ((size_t)m * K_) * DG_;
#pragma unroll
        for (int j = 0; j < 8; j++) {
            unsigned b = __ballot_sync(0xFFFFFFFFu, l[j] >= thresh);
            while (b) {
                int src = __ffs(b) - 1; b &= b - 1;
                int k = src * 8 + j;
                const float* kh = kph + (size_t)k * DG_;
                const float* kl = kpl + (size_t)k * DG_;
                dd a; a.h = a.l = 0.f;
#pragma unroll
                for (int ci = 0; ci < 4; ci++) {
                    int c = lane + 32 * ci;
                    dd kp; kp.h = kh[c]; kp.l = kl[c];
                    dd qp; qp.h = qh_s[wid][c]; qp.l = ql_s[wid][c];
                    a = dd_add(a, dd_mul(kp, qp));
                }
                double v = (double)a.h + (double)a.l;
#pragma unroll
                for (int o = 16; o > 0; o >>= 1) v += __shfl_xor_sync(0xFFFFFFFFu, v, o);
                if (v > bestv || (v == bestv && k < besti)) { bestv = v; besti = k; }
            }
        }
        if (lane == 0) code_out[(size_t)pg * M_ + m] = (float)besti;
    }
}

extern "C" void kernel_launch(void* const* d_in, const int* in_sizes, int n_in,
                              void* d_out, int out_size) {
    const float* latent   = (const float*)d_in[0];
    const float* codebook = (const float*)d_in[1];
    const float* wq       = (const float*)d_in[2];
    const float* wk       = (const float*)d_in[3];
    const float* wv       = (const float*)d_in[4];
    const float* unif     = (const float*)d_in[5];
    float* out   = (float*)d_out;
    float* quant = out;
    float* code  = out + QUANT_ELEMS;
    float* logit = out + QUANT_ELEMS + CODE_ELEMS;

    precompute_kernel<<<dim3(K_ / 8, M_), 256>>>(codebook, wq, wk, wv);
    cudaFuncSetAttribute(main_kernel, cudaFuncAttributeMaxDynamicSharedMemorySize, SMEM_TOTAL);
    main_kernel<<<dim3(NPIX_ / 64, M_), 256, SMEM_TOTAL>>>(latent, unif, quant, code, logit);
    refine_kernel<<<256, 128>>>(latent, wq, logit, code);
}

// round 13
// speedup vs baseline: 1.1154x; 1.1154x over previous
#include <cuda_runtime.h>
#include <cuda_fp16.h>
#include <cstdint>

#define M_    8
#define K_    256
#define DG_   128
#define D_    1024
#define HW_   1024
#define NPIX_ 32768
#define QUANT_ELEMS 33554432
#define CODE_ELEMS  262144
#define GAP_THRESH 5e-3f
#define REF_WIN    8e-3f
#define CAP_       32768

__device__ unsigned short g_Eh[M_ * K_ * DG_];   // E [m][k][d] fp16
__device__ unsigned short g_Vh[M_ * DG_ * K_];   // Vt [m][d][k] fp16
__device__ float g_KPH[M_ * K_ * DG_];
__device__ float g_KPL[M_ * K_ * DG_];
__device__ int   g_count;
__device__ int   g_list[CAP_];

__device__ __forceinline__ uint32_t smem_to_u32(const void* p) {
    uint32_t a;
    asm("{ .reg .u64 t; cvta.to.shared.u64 t, %1; cvt.u32.u64 %0, t; }" : "=r"(a) : "l"(p));
    return a;
}
__device__ __forceinline__ void ldsm4(uint32_t* r, uint32_t addr) {
    asm volatile("ldmatrix.sync.aligned.m8n8.x4.shared.b16 {%0,%1,%2,%3}, [%4];"
        : "=r"(r[0]), "=r"(r[1]), "=r"(r[2]), "=r"(r[3]) : "r"(addr));
}
__device__ __forceinline__ void mma_f16(float* d, const uint32_t* a, const uint32_t* b) {
    asm volatile("mma.sync.aligned.m16n8k16.row.col.f32.f16.f16.f32 "
        "{%0,%1,%2,%3}, {%4,%5,%6,%7}, {%8,%9}, {%0,%1,%2,%3};"
        : "+f"(d[0]), "+f"(d[1]), "+f"(d[2]), "+f"(d[3])
        : "r"(a[0]), "r"(a[1]), "r"(a[2]), "r"(a[3]), "r"(b[0]), "r"(b[1]));
}

struct dd { float h, l; };
__device__ __forceinline__ dd two_sum(float a, float b) {
    float s = __fadd_rn(a, b), bb = __fsub_rn(s, a);
    float e = __fadd_rn(__fsub_rn(a, __fsub_rn(s, bb)), __fsub_rn(b, bb));
    dd r; r.h = s; r.l = e; return r;
}
__device__ __forceinline__ dd two_prod(float a, float b) {
    float p = __fmul_rn(a, b), e = __fmaf_rn(a, b, -p);
    dd r; r.h = p; r.l = e; return r;
}
__device__ __forceinline__ dd dd_add(dd x, dd y) {
    dd s = two_sum(x.h, y.h);
    float lo = __fadd_rn(__fadd_rn(x.l, y.l), s.l);
    float hi = __fadd_rn(s.h, lo);
    float l = __fadd_rn(__fsub_rn(s.h, hi), lo);
    dd r; r.h = hi; r.l = l; return r;
}
__device__ __forceinline__ dd dd_fma(dd a, float x, float y) { return dd_add(a, two_prod(x, y)); }
__device__ __forceinline__ dd dd_mul(dd x, dd y) {
    dd p = two_prod(x.h, y.h);
    float t = __fmaf_rn(x.h, y.l, p.l); t = __fmaf_rn(x.l, y.h, t);
    float hi = __fadd_rn(p.h, t), l = __fadd_rn(__fsub_rn(p.h, hi), t);
    dd r; r.h = hi; r.l = l; return r;
}
__device__ __forceinline__ float neglog_acc(float u) {
    float t = __fsub_rn(u, 1.0f);
    float p = fmaf(t, 0.142857143f, -0.166666667f);
    p = fmaf(t, p, 0.2f); p = fmaf(t, p, -0.25f);
    p = fmaf(t, p, 0.333333333f); p = fmaf(t, p, -0.5f); p = fmaf(t, p, 1.0f);
    return (u > 0.75f) ? -(t * p) : -__logf(u);
}

// ---------------- precompute: kproj(dd), Vt/E fp16 ----------------
// grid (K_/4 = 64, M_), 256 threads; 4 k-values per block (2x parallelism vs prior).
#define P_CB 0
#define P_KP 512
#define P_WK 1024
#define P_WV (1024 + 4224)
#define P_WQ 1024
#define P_FLOATS (1024 + 4224 + 4224)

__global__ void __launch_bounds__(256)
precompute_kernel(const float* __restrict__ codebook, const float* __restrict__ wq,
                  const float* __restrict__ wk, const float* __restrict__ wv) {
    __shared__ float sm[P_FLOATS];
    float *cbs = sm + P_CB, *kps = sm + P_KP, *wks = sm + P_WK, *wvs = sm + P_WV, *wqs = sm + P_WQ;
    const int m = blockIdx.y, k0 = blockIdx.x * 4, tid = threadIdx.x;
    const int c = tid & 127, khalf = tid >> 7;
    if (m == 0 && blockIdx.x == 0 && tid == 0) g_count = 0;
#pragma unroll
    for (int r = 0; r < 2; r++) {
        int idx = tid + 256 * r;
        cbs[idx] = codebook[((size_t)m * K_ + k0) * DG_ + idx];
    }
    dd sk[2]; float sv[2];
#pragma unroll
    for (int i = 0; i < 2; i++) { sk[i].h = sk[i].l = 0.f; sv[i] = 0.f; }
    const float* wkm = wk + (size_t)m * DG_ * DG_;
    const float* wvm = wv + (size_t)m * DG_ * DG_;
    for (int dc = 0; dc < DG_; dc += 32) {
        __syncthreads();
#pragma unroll
        for (int r = 0; r < 16; r++) {
            int idx = tid + 256 * r, cc = idx >> 5, j = idx & 31;
            wks[cc * 33 + j] = wkm[(size_t)cc * DG_ + dc + j];
            wvs[cc * 33 + j] = wvm[(size_t)cc * DG_ + dc + j];
        }
        __syncthreads();
#pragma unroll 4
        for (int j = 0; j < 32; j++) {
            float wkv = wks[c * 33 + j], wvv = wvs[c * 33 + j];
#pragma unroll
            for (int i = 0; i < 2; i++) {
                float cbv = cbs[(khalf * 2 + i) * DG_ + dc + j];
                sk[i] = dd_fma(sk[i], cbv, wkv);
                sv[i] = fmaf(cbv, wvv, sv[i]);
            }
        }
    }
#pragma unroll
    for (int i = 0; i < 2; i++) {
        int kk = k0 + khalf * 2 + i;
        size_t gb = ((size_t)m * K_ + kk) * DG_ + c;
        g_KPH[gb] = sk[i].h; g_KPL[gb] = sk[i].l;
        g_Vh[((size_t)m * DG_ + c) * K_ + kk] = __half_as_ushort(__float2half_rn(sv[i]));
        kps[(khalf * 2 + i) * DG_ + c] = sk[i].h;
    }
    const int d = c;
    float ea[2] = {0.f, 0.f};
    const float* wqm = wq + (size_t)m * DG_ * DG_;
    for (int c0 = 0; c0 < DG_; c0 += 32) {
        __syncthreads();
#pragma unroll
        for (int r = 0; r < 16; r++) {
            int idx = tid + 256 * r;
            wqs[idx] = wqm[(size_t)c0 * DG_ + idx];
        }
        __syncthreads();
#pragma unroll 4
        for (int cc = 0; cc < 32; cc++) {
            float wv_ = wqs[cc * DG_ + d];
#pragma unroll
            for (int i = 0; i < 2; i++)
                ea[i] = fmaf(kps[(khalf * 2 + i) * DG_ + c0 + cc], wv_, ea[i]);
        }
    }
#pragma unroll
    for (int i = 0; i < 2; i++)
        g_Eh[((size_t)m * K_ + k0 + khalf * 2 + i) * DG_ + d] =
            __half_as_ushort(__float2half_rn(ea[i]));
}

// ---------------- main mma.sync kernel: 64 pix x fixed m, 2 CTAs/SM ----------------
// (byte-identical to the 518.5us round-11 kernel)
#define SM_B1S  0
#define SM_B2S  512
#define SM_I1S  1024
#define SM_SUMS 1536
#define SM_RI   2048
#define SM_SSH  4096
#define SM_STG  37888
#define SM_AH   (SM_STG)
#define SM_EH   (SM_STG + 3072)
#define SM_VH   (SM_STG)
#define SM_QB   (SM_STG)
#define SMEM_TOTAL (37888 + 33792)   // 71680

#define UPD(b1, b2, i1, v, k) do { \
    if ((v) > (b1)) { b2 = b1; b1 = (v); i1 = (k); } \
    else if ((v) > (b2)) b2 = (v); } while (0)

#define LOAD_A(c8) do { _Pragma("unroll") \
    for (int j = 0; j < 2; j++) { \
        int dp = (tid >> 6) + 4 * j, pix = tid & 63; \
        pfA[2 * j]     = latb[(size_t)(16 * (c8) + 2 * dp) * HW_ + pix]; \
        pfA[2 * j + 1] = latb[(size_t)(16 * (c8) + 2 * dp + 1) * HW_ + pix]; \
    } } while (0)
#define LOAD_E(c8) do { _Pragma("unroll") \
    for (int j = 0; j < 2; j++) pfE[j] = ebH[(size_t)tid * 16 + (c8) * 2 + j]; \
    } while (0)
#define STORE_AE() do { _Pragma("unroll") \
    for (int j = 0; j < 2; j++) { \
        int dp = (tid >> 6) + 4 * j, pix = tid & 63; \
        unsigned short h0 = __half_as_ushort(__float2half_rn(pfA[2 * j])); \
        unsigned short h1 = __half_as_ushort(__float2half_rn(pfA[2 * j + 1])); \
        *(uint32_t*)(smem + SM_AH + pix * 48 + dp * 4) = ((uint32_t)h1 << 16) | h0; \
        *(uint4*)(smem + SM_EH + tid * 48 + j * 16) = pfE[j]; \
    } } while (0)
#define LOAD_V(it) do { _Pragma("unroll") \
    for (int jj = 0; jj < 2; jj++) { \
        int q = tid + 256 * jj; \
        pfV[jj] = vtH[(size_t)(q >> 2) * 32 + (it) * 4 + (q & 3)]; \
    } } while (0)
#define STORE_V() do { _Pragma("unroll") \
    for (int jj = 0; jj < 2; jj++) { \
        int q = tid + 256 * jj, dR = q >> 2, kc = q & 3; \
        *(uint4*)(smem + SM_VH + dR * 80 + kc * 16) = pfV[jj]; \
    } } while (0)

__global__ void __launch_bounds__(256, 2)
main_kernel(const float* __restrict__ latent, const float* __restrict__ unif,
            float* __restrict__ quant_out, float* __restrict__ code_out,
            float* __restrict__ logit_out) {
    extern __shared__ char smem[];
    const uint32_t sb = smem_to_u32(smem);
    const int m = blockIdx.y, p0 = blockIdx.x * 64;
    const int n = p0 >> 10, s0 = p0 & 1023;
    const int tid = threadIdx.x, w = tid >> 5, lane = tid & 31;
    const int wp = w >> 1, wk = w & 1;
    const int gid = lane >> 2, tig = lane & 3;
    const int li = lane & 7, lg = lane >> 3;

    float* b1s = (float*)(smem + SM_B1S);
    float* b2s = (float*)(smem + SM_B2S);
    int*   i1s = (int*)(smem + SM_I1S);
    float* sums = (float*)(smem + SM_SUMS);
    float* rinv = (float*)(smem + SM_RI);
    float* qbuf = (float*)(smem + SM_QB);

    const int a_row = wp * 16 + ((lg & 1) << 3) + li;
    const int a_col = ((lg >> 1) << 3);
    const int b_row = ((lg >> 1) << 3) + li;
    const int b_col = ((lg & 1) << 3);
    const uint32_t aAh = sb + SM_AH + a_row * 48 + a_col * 2;
    const uint32_t aEh = sb + SM_EH + (wk * 128 + b_row) * 48 + b_col * 2;

    const float* latb = latent + ((size_t)n * D_ + (size_t)m * DG_) * HW_ + s0;
    const uint4* ebH = (const uint4*)(g_Eh + (size_t)m * K_ * DG_);
    const uint4* vtH = (const uint4*)(g_Vh + (size_t)m * DG_ * K_);

    // ================= GEMM1: logits[64 pix][256 k], single fp16 product =================
    float acc[16][4];
#pragma unroll
    for (int i = 0; i < 16; i++)
#pragma unroll
        for (int j = 0; j < 4; j++) acc[i][j] = 0.f;

    float pfA[4];
    uint4 pfE[2];
    LOAD_A(0); LOAD_E(0);

    for (int c8 = 0; c8 < 8; c8++) {
        STORE_AE();
        __syncthreads();
        if (c8 < 7) { LOAD_A(c8 + 1); LOAD_E(c8 + 1); }
        uint32_t ah[4];
        ldsm4(ah, aAh);
#pragma unroll
        for (int nf2 = 0; nf2 < 8; nf2++) {
            uint32_t bh[4];
            ldsm4(bh, aEh + nf2 * 768);
            mma_f16(acc[2 * nf2], ah, bh);
            mma_f16(acc[2 * nf2 + 1], ah, bh + 2);
        }
        __syncthreads();
    }

    // ================= Epilogue pass 1: logits out, top-2, e -> acc =================
    const int p_r = wp * 16 + gid;
    const size_t pgA = (size_t)(p0 + p_r), pgB = pgA + 8;
    float* lpA = logit_out + (pgA * M_ + m) * K_ + wk * 128 + 2 * tig;
    float* lpB = logit_out + (pgB * M_ + m) * K_ + wk * 128 + 2 * tig;
    const float* upA = unif + (pgA * M_ + m) * K_ + wk * 128 + 2 * tig;
    const float* upB = unif + (pgB * M_ + m) * K_ + wk * 128 + 2 * tig;

    float b1r[2] = {-3.4e38f, -3.4e38f}, b2r[2] = {-3.4e38f, -3.4e38f};
    int i1r[2] = {0, 0};
    float sumr[2] = {0.f, 0.f};

#pragma unroll
    for (int nf = 0; nf < 16; nf++) {
        int kk = wk * 128 + nf * 8 + 2 * tig;
        float l00 = acc[nf][0], l01 = acc[nf][1], l10 = acc[nf][2], l11 = acc[nf][3];
        *(float2*)(lpA + nf * 8) = make_float2(l00, l01);
        *(float2*)(lpB + nf * 8) = make_float2(l10, l11);
        float2 u0 = *(const float2*)(upA + nf * 8);
        float2 u1 = *(const float2*)(upB + nf * 8);
        UPD(b1r[0], b2r[0], i1r[0], l00, kk);
        UPD(b1r[0], b2r[0], i1r[0], l01, kk + 1);
        UPD(b1r[1], b2r[1], i1r[1], l10, kk);
        UPD(b1r[1], b2r[1], i1r[1], l11, kk + 1);
        float e00 = __fdividef(__expf(l00), neglog_acc(u0.x));
        float e01 = __fdividef(__expf(l01), neglog_acc(u0.y));
        float e10 = __fdividef(__expf(l10), neglog_acc(u1.x));
        float e11 = __fdividef(__expf(l11), neglog_acc(u1.y));
        sumr[0] += e00 + e01;
        sumr[1] += e10 + e11;
        acc[nf][0] = e00; acc[nf][1] = e01; acc[nf][2] = e10; acc[nf][3] = e11;
    }

    uint4 pfV[2];
    LOAD_V(0);

#pragma unroll
    for (int r = 0; r < 2; r++) {
#pragma unroll
        for (int o = 1; o <= 2; o <<= 1) {
            float ob1 = __shfl_xor_sync(0xFFFFFFFFu, b1r[r], o);
            int   oi1 = __shfl_xor_sync(0xFFFFFFFFu, i1r[r], o);
            float ob2 = __shfl_xor_sync(0xFFFFFFFFu, b2r[r], o);
            if (ob1 > b1r[r] || (ob1 == b1r[r] && oi1 < i1r[r])) {
                b2r[r] = fmaxf(b1r[r], ob2); b1r[r] = ob1; i1r[r] = oi1;
            } else b2r[r] = fmaxf(b2r[r], ob1);
            sumr[r] += __shfl_xor_sync(0xFFFFFFFFu, sumr[r], o);
        }
    }
    if (tig == 0) {
        b1s[wk * 64 + p_r] = b1r[0];  b1s[wk * 64 + p_r + 8] = b1r[1];
        b2s[wk * 64 + p_r] = b2r[0];  b2s[wk * 64 + p_r + 8] = b2r[1];
        i1s[wk * 64 + p_r] = i1r[0];  i1s[wk * 64 + p_r + 8] = i1r[1];
        sums[wk * 64 + p_r] = sumr[0]; sums[wk * 64 + p_r + 8] = sumr[1];
    }
    __syncthreads();

    if (tid < 64) {
        const int p = tid;
        const size_t pg = (size_t)(p0 + p);
        float a1 = b1s[p], a2 = b2s[p];           int ai = i1s[p];
        float c1 = b1s[64 + p], c2 = b2s[64 + p]; int ci = i1s[64 + p];
        float b1, b2; int i1;
        if (a1 >= c1) { b1 = a1; i1 = ai; b2 = fmaxf(a2, fmaxf(c1, c2)); }
        else          { b1 = c1; i1 = ci; b2 = fmaxf(c2, fmaxf(a1, a2)); }
        rinv[p] = 1.0f / (sums[p] + sums[64 + p]);
        code_out[pg * M_ + m] = (float)i1;
        if (b1 - b2 < GAP_THRESH) {
            int idx = atomicAdd(&g_count, 1);
            if (idx < CAP_) g_list[idx] = (int)(pg * M_ + m);
        }
    }
    __syncthreads();

    // ================= Epilogue pass 2: normalize S -> fp16 smem =================
    {
        const float riA = rinv[p_r], riB = rinv[p_r + 8];
#pragma unroll
        for (int nf = 0; nf < 16; nf++) {
            int kk = wk * 128 + nf * 8 + 2 * tig;
            unsigned short h00 = __half_as_ushort(__float2half_rn(acc[nf][0] * riA));
            unsigned short h01 = __half_as_ushort(__float2half_rn(acc[nf][1] * riA));
            unsigned short h10 = __half_as_ushort(__float2half_rn(acc[nf][2] * riB));
            unsigned short h11 = __half_as_ushort(__float2half_rn(acc[nf][3] * riB));
            *(uint32_t*)(smem + SM_SSH + p_r * 528 + kk * 2)       = ((uint32_t)h01 << 16) | h00;
            *(uint32_t*)(smem + SM_SSH + (p_r + 8) * 528 + kk * 2) = ((uint32_t)h11 << 16) | h10;
        }
    }

    // ================= GEMM2: quant[64 pix][128 d] = S_norm x Vt^T =================
    float acc2[8][4];
#pragma unroll
    for (int i = 0; i < 8; i++)
#pragma unroll
        for (int j = 0; j < 4; j++) acc2[i][j] = 0.f;

    const uint32_t aSh = sb + SM_SSH + a_row * 528 + a_col * 2;
    const uint32_t bvh = sb + SM_VH + (wk * 64 + b_row) * 80 + b_col * 2;

    for (int it = 0; it < 8; it++) {
        STORE_V();
        __syncthreads();
        if (it < 7) LOAD_V(it + 1);
#pragma unroll
        for (int s = 0; s < 2; s++) {
            const int k0 = it * 32 + s * 16;
            uint32_t sh[4];
            ldsm4(sh, aSh + k0 * 2);
#pragma unroll
            for (int nf2 = 0; nf2 < 4; nf2++) {
                uint32_t bh[4];
                ldsm4(bh, bvh + nf2 * 1280 + s * 32);
                mma_f16(acc2[2 * nf2], sh, bh);
                mma_f16(acc2[2 * nf2 + 1], sh, bh + 2);
            }
        }
        __syncthreads();
    }

#pragma unroll
    for (int nf = 0; nf < 8; nf++) {
        int d = wk * 64 + 8 * nf + 2 * tig;
        qbuf[p_r * 132 + d]       = acc2[nf][0];
        qbuf[p_r * 132 + d + 1]   = acc2[nf][1];
        qbuf[(p_r + 8) * 132 + d]     = acc2[nf][2];
        qbuf[(p_r + 8) * 132 + d + 1] = acc2[nf][3];
    }
    __syncthreads();
    {
        const int pix = tid & 63, dg2 = tid >> 6;
        float* qb = quant_out + ((size_t)n * D_ + (size_t)m * DG_) * HW_ + s0 + pix;
#pragma unroll
        for (int j = 0; j < 32; j++) {
            int d = dg2 * 32 + j;
            qb[(size_t)d * HW_] = qbuf[pix * 132 + d];
        }
    }
}

// ---------------- refine: dd-exact argmax for near-tie pixels ----------------
__global__ void __launch_bounds__(128)
refine_kernel(const float* __restrict__ latent, const float* __restrict__ wq,
              const float* __restrict__ logit_out, float* __restrict__ code_out) {
    __shared__ float qv_s[4][DG_], qh_s[4][DG_], ql_s[4][DG_];
    const int wid = threadIdx.x >> 5, lane = threadIdx.x & 31;
    const int gw = blockIdx.x * 4 + wid, tw = gridDim.x * 4;
    int cnt = g_count; if (cnt > CAP_) cnt = CAP_;
    for (int e = gw; e < cnt; e += tw) {
        int ent = g_list[e], m = ent & 7, pg = ent >> 3;
        int n = pg >> 10, s = pg & 1023;
        const float* latb = latent + ((size_t)n * D_ + (size_t)m * DG_) * HW_ + s;
        for (int d = lane; d < DG_; d += 32) qv_s[wid][d] = latb[(size_t)d * HW_];
        __syncwarp();
        const float* wqm = wq + (size_t)m * DG_ * DG_;
#pragma unroll
        for (int ci = 0; ci < 4; ci++) {
            int c = lane + 32 * ci;
            const float* wr = wqm + (size_t)c * DG_;
            dd a; a.h = a.l = 0.f;
            for (int d = 0; d < DG_; d++) a = dd_fma(a, qv_s[wid][d], wr[d]);
            qh_s[wid][c] = a.h; ql_s[wid][c] = a.l;
        }
        __syncwarp();
        const float* lo = logit_out + ((size_t)pg * M_ + m) * K_;
        float l[8], fm = -3.4e38f;
#pragma unroll
        for (int j = 0; j < 8; j++) { l[j] = lo[lane * 8 + j]; fm = fmaxf(fm, l[j]); }
#pragma unroll
        for (int o = 16; o > 0; o >>= 1) fm = fmaxf(fm, __shfl_xor_sync(0xFFFFFFFFu, fm, o));
        float thresh = fm - REF_WIN;
        double bestv = -1e300; int besti = 1 << 30;
        const float* kph = g_KPH + ((size_t)m * K_) * DG_;
        const float* kpl = g_KPL + ((size_t)m * K_) * DG_;
#pragma unroll
        for (int j = 0; j < 8; j++) {
            unsigned b = __ballot_sync(0xFFFFFFFFu, l[j] >= thresh);
            while (b) {
                int src = __ffs(b) - 1; b &= b - 1;
                int k = src * 8 + j;
                const float* kh = kph + (size_t)k * DG_;
                const float* kl = kpl + (size_t)k * DG_;
                dd a; a.h = a.l = 0.f;
#pragma unroll
                for (int ci = 0; ci < 4; ci++) {
                    int c = lane + 32 * ci;
                    dd kp; kp.h = kh[c]; kp.l = kl[c];
                    dd qp; qp.h = qh_s[wid][c]; qp.l = ql_s[wid][c];
                    a = dd_add(a, dd_mul(kp, qp));
                }
                double v = (double)a.h + (double)a.l;
#pragma unroll
                for (int o = 16; o > 0; o >>= 1) v += __shfl_xor_sync(0xFFFFFFFFu, v, o);
                if (v > bestv || (v == bestv && k < besti)) { bestv = v; besti = k; }
            }
        }
        if (lane == 0) code_out[(size_t)pg * M_ + m] = (float)besti;
    }
}

extern "C" void kernel_launch(void* const* d_in, const int* in_sizes, int n_in,
                              void* d_out, int out_size) {
    const float* latent   = (const float*)d_in[0];
    const float* codebook = (const float*)d_in[1];
    const float* wq       = (const float*)d_in[2];
    const float* wk       = (const float*)d_in[3];
    const float* wv       = (const float*)d_in[4];
    const float* unif     = (const float*)d_in[5];
    float* out   = (float*)d_out;
    float* quant = out;
    float* code  = out + QUANT_ELEMS;
    float* logit = out + QUANT_ELEMS + CODE_ELEMS;

    precompute_kernel<<<dim3(K_ / 4, M_), 256>>>(codebook, wq, wk, wv);
    cudaFuncSetAttribute(main_kernel, cudaFuncAttributeMaxDynamicSharedMemorySize, SMEM_TOTAL);
    main_kernel<<<dim3(NPIX_ / 64, M_), 256, SMEM_TOTAL>>>(latent, unif, quant, code, logit);
    refine_kernel<<<256, 128>>>(latent, wq, logit, code);
}

// round 14
// speedup vs baseline: 1.1572x; 1.0374x over previous
#include <cuda_runtime.h>
#include <cuda_fp16.h>
#include <cstdint>

#define M_    8
#define K_    256
#define DG_   128
#define D_    1024
#define HW_   1024
#define NPIX_ 32768
#define QUANT_ELEMS 33554432
#define CODE_ELEMS  262144
#define GAP_THRESH 5e-3f
#define REF_WIN    8e-3f
#define CAP_       32768

__device__ unsigned short g_Eh[M_ * K_ * DG_];   // E [m][k][d] fp16
__device__ unsigned short g_Vh[M_ * DG_ * K_];   // Vt [m][d][k] fp16
__device__ float g_KPH[M_ * K_ * DG_];
__device__ float g_KPL[M_ * K_ * DG_];
__device__ int   g_count;
__device__ int   g_list[CAP_];

__device__ __forceinline__ uint32_t smem_to_u32(const void* p) {
    uint32_t a;
    asm("{ .reg .u64 t; cvta.to.shared.u64 t, %1; cvt.u32.u64 %0, t; }" : "=r"(a) : "l"(p));
    return a;
}
__device__ __forceinline__ void ldsm4(uint32_t* r, uint32_t addr) {
    asm volatile("ldmatrix.sync.aligned.m8n8.x4.shared.b16 {%0,%1,%2,%3}, [%4];"
        : "=r"(r[0]), "=r"(r[1]), "=r"(r[2]), "=r"(r[3]) : "r"(addr));
}
__device__ __forceinline__ void mma_f16(float* d, const uint32_t* a, const uint32_t* b) {
    asm volatile("mma.sync.aligned.m16n8k16.row.col.f32.f16.f16.f32 "
        "{%0,%1,%2,%3}, {%4,%5,%6,%7}, {%8,%9}, {%0,%1,%2,%3};"
        : "+f"(d[0]), "+f"(d[1]), "+f"(d[2]), "+f"(d[3])
        : "r"(a[0]), "r"(a[1]), "r"(a[2]), "r"(a[3]), "r"(b[0]), "r"(b[1]));
}
#define CP16(dst, src) \
    asm volatile("cp.async.cg.shared.global [%0], [%1], 16;" :: "r"(dst), "l"(src) : "memory")
#define CP_COMMIT() asm volatile("cp.async.commit_group;" ::: "memory")
#define CP_WAIT0()  asm volatile("cp.async.wait_group 0;" ::: "memory")

struct dd { float h, l; };
__device__ __forceinline__ dd two_sum(float a, float b) {
    float s = __fadd_rn(a, b), bb = __fsub_rn(s, a);
    float e = __fadd_rn(__fsub_rn(a, __fsub_rn(s, bb)), __fsub_rn(b, bb));
    dd r; r.h = s; r.l = e; return r;
}
__device__ __forceinline__ dd two_prod(float a, float b) {
    float p = __fmul_rn(a, b), e = __fmaf_rn(a, b, -p);
    dd r; r.h = p; r.l = e; return r;
}
__device__ __forceinline__ dd dd_add(dd x, dd y) {
    dd s = two_sum(x.h, y.h);
    float lo = __fadd_rn(__fadd_rn(x.l, y.l), s.l);
    float hi = __fadd_rn(s.h, lo);
    float l = __fadd_rn(__fsub_rn(s.h, hi), lo);
    dd r; r.h = hi; r.l = l; return r;
}
__device__ __forceinline__ dd dd_fma(dd a, float x, float y) { return dd_add(a, two_prod(x, y)); }
__device__ __forceinline__ dd dd_mul(dd x, dd y) {
    dd p = two_prod(x.h, y.h);
    float t = __fmaf_rn(x.h, y.l, p.l); t = __fmaf_rn(x.l, y.h, t);
    float hi = __fadd_rn(p.h, t), l = __fadd_rn(__fsub_rn(p.h, hi), t);
    dd r; r.h = hi; r.l = l; return r;
}
__device__ __forceinline__ float neglog_acc(float u) {
    float t = __fsub_rn(u, 1.0f);
    float p = fmaf(t, 0.142857143f, -0.166666667f);
    p = fmaf(t, p, 0.2f); p = fmaf(t, p, -0.25f);
    p = fmaf(t, p, 0.333333333f); p = fmaf(t, p, -0.5f); p = fmaf(t, p, 1.0f);
    return (u > 0.75f) ? -(t * p) : -__logf(u);
}

// ---------------- precompute: kproj(dd), Vt/E fp16 (R13 config) ----------------
#define P_CB 0
#define P_KP 512
#define P_WK 1024
#define P_WV (1024 + 4224)
#define P_WQ 1024
#define P_FLOATS (1024 + 4224 + 4224)

__global__ void __launch_bounds__(256)
precompute_kernel(const float* __restrict__ codebook, const float* __restrict__ wq,
                  const float* __restrict__ wk, const float* __restrict__ wv) {
    __shared__ float sm[P_FLOATS];
    float *cbs = sm + P_CB, *kps = sm + P_KP, *wks = sm + P_WK, *wvs = sm + P_WV, *wqs = sm + P_WQ;
    const int m = blockIdx.y, k0 = blockIdx.x * 4, tid = threadIdx.x;
    const int c = tid & 127, khalf = tid >> 7;
    if (m == 0 && blockIdx.x == 0 && tid == 0) g_count = 0;
#pragma unroll
    for (int r = 0; r < 2; r++) {
        int idx = tid + 256 * r;
        cbs[idx] = codebook[((size_t)m * K_ + k0) * DG_ + idx];
    }
    dd sk[2]; float sv[2];
#pragma unroll
    for (int i = 0; i < 2; i++) { sk[i].h = sk[i].l = 0.f; sv[i] = 0.f; }
    const float* wkm = wk + (size_t)m * DG_ * DG_;
    const float* wvm = wv + (size_t)m * DG_ * DG_;
    for (int dc = 0; dc < DG_; dc += 32) {
        __syncthreads();
#pragma unroll
        for (int r = 0; r < 16; r++) {
            int idx = tid + 256 * r, cc = idx >> 5, j = idx & 31;
            wks[cc * 33 + j] = wkm[(size_t)cc * DG_ + dc + j];
            wvs[cc * 33 + j] = wvm[(size_t)cc * DG_ + dc + j];
        }
        __syncthreads();
#pragma unroll 4
        for (int j = 0; j < 32; j++) {
            float wkv = wks[c * 33 + j], wvv = wvs[c * 33 + j];
#pragma unroll
            for (int i = 0; i < 2; i++) {
                float cbv = cbs[(khalf * 2 + i) * DG_ + dc + j];
                sk[i] = dd_fma(sk[i], cbv, wkv);
                sv[i] = fmaf(cbv, wvv, sv[i]);
            }
        }
    }
#pragma unroll
    for (int i = 0; i < 2; i++) {
        int kk = k0 + khalf * 2 + i;
        size_t gb = ((size_t)m * K_ + kk) * DG_ + c;
        g_KPH[gb] = sk[i].h; g_KPL[gb] = sk[i].l;
        g_Vh[((size_t)m * DG_ + c) * K_ + kk] = __half_as_ushort(__float2half_rn(sv[i]));
        kps[(khalf * 2 + i) * DG_ + c] = sk[i].h;
    }
    const int d = c;
    float ea[2] = {0.f, 0.f};
    const float* wqm = wq + (size_t)m * DG_ * DG_;
    for (int c0 = 0; c0 < DG_; c0 += 32) {
        __syncthreads();
#pragma unroll
        for (int r = 0; r < 16; r++) {
            int idx = tid + 256 * r;
            wqs[idx] = wqm[(size_t)c0 * DG_ + idx];
        }
        __syncthreads();
#pragma unroll 4
        for (int cc = 0; cc < 32; cc++) {
            float wv_ = wqs[cc * DG_ + d];
#pragma unroll
            for (int i = 0; i < 2; i++)
                ea[i] = fmaf(kps[(khalf * 2 + i) * DG_ + c0 + cc], wv_, ea[i]);
        }
    }
#pragma unroll
    for (int i = 0; i < 2; i++)
        g_Eh[((size_t)m * K_ + k0 + khalf * 2 + i) * DG_ + d] =
            __half_as_ushort(__float2half_rn(ea[i]));
}

// ---------------- main mma.sync kernel: 64 pix x fixed m, 2 CTAs/SM ----------------
// smem map (bytes):
//  [0..4096)         small buffers
//  [4096..37888)     S (normalized) fp16 [64][528B rows]
//  [37888..71680)    stage: A0/A1 (2x3072) + E0/E1 (2x12288) = 30720
//                     / V0/V1 (2x10240) / qbuf[64][132]f32 = 33792
#define SM_B1S  0
#define SM_B2S  512
#define SM_I1S  1024
#define SM_SUMS 1536
#define SM_RI   2048
#define SM_SSH  4096
#define SM_STG  37888
#define SM_AH   (SM_STG)
#define SM_EH   (SM_STG + 6144)
#define SM_VH   (SM_STG)
#define SM_QB   (SM_STG)
#define SMEM_TOTAL (37888 + 33792)   // 71680

#define UPD(b1, b2, i1, v, k) do { \
    if ((v) > (b1)) { b2 = b1; b1 = (v); i1 = (k); } \
    else if ((v) > (b2)) b2 = (v); } while (0)

#define LOAD_A(c8) do { _Pragma("unroll") \
    for (int j = 0; j < 2; j++) { \
        int dp = (tid >> 6) + 4 * j, pix = tid & 63; \
        pfA[2 * j]     = latb[(size_t)(16 * (c8) + 2 * dp) * HW_ + pix]; \
        pfA[2 * j + 1] = latb[(size_t)(16 * (c8) + 2 * dp + 1) * HW_ + pix]; \
    } } while (0)
#define STS_A(buf) do { char* ab = smem + SM_AH + (buf) * 3072; _Pragma("unroll") \
    for (int j = 0; j < 2; j++) { \
        int dp = (tid >> 6) + 4 * j, pix = tid & 63; \
        unsigned short h0 = __half_as_ushort(__float2half_rn(pfA[2 * j])); \
        unsigned short h1 = __half_as_ushort(__float2half_rn(pfA[2 * j + 1])); \
        *(uint32_t*)(ab + pix * 48 + dp * 4) = ((uint32_t)h1 << 16) | h0; \
    } } while (0)
#define CP_E(c8, buf) do { uint32_t eb = sb + SM_EH + (buf) * 12288; _Pragma("unroll") \
    for (int j = 0; j < 2; j++) \
        CP16(eb + tid * 48 + j * 16, ebH + (size_t)tid * 16 + (c8) * 2 + j); \
    } while (0)
#define CP_V(it, buf) do { uint32_t vb = sb + SM_VH + (buf) * 10240; _Pragma("unroll") \
    for (int jj = 0; jj < 2; jj++) { \
        int q = tid + 256 * jj; \
        CP16(vb + (q >> 2) * 80 + (q & 3) * 16, vtH + (size_t)(q >> 2) * 32 + (it) * 4 + (q & 3)); \
    } } while (0)

__global__ void __launch_bounds__(256, 2)
main_kernel(const float* __restrict__ latent, const float* __restrict__ unif,
            float* __restrict__ quant_out, float* __restrict__ code_out,
            float* __restrict__ logit_out) {
    extern __shared__ char smem[];
    const uint32_t sb = smem_to_u32(smem);
    const int m = blockIdx.y, p0 = blockIdx.x * 64;
    const int n = p0 >> 10, s0 = p0 & 1023;
    const int tid = threadIdx.x, w = tid >> 5, lane = tid & 31;
    const int wp = w >> 1, wk = w & 1;
    const int gid = lane >> 2, tig = lane & 3;
    const int li = lane & 7, lg = lane >> 3;

    float* b1s = (float*)(smem + SM_B1S);
    float* b2s = (float*)(smem + SM_B2S);
    int*   i1s = (int*)(smem + SM_I1S);
    float* sums = (float*)(smem + SM_SUMS);
    float* rinv = (float*)(smem + SM_RI);
    float* qbuf = (float*)(smem + SM_QB);

    const int a_row = wp * 16 + ((lg & 1) << 3) + li;
    const int a_col = ((lg >> 1) << 3);
    const int b_row = ((lg >> 1) << 3) + li;
    const int b_col = ((lg & 1) << 3);
    const uint32_t aAh = sb + SM_AH + a_row * 48 + a_col * 2;
    const uint32_t aEh = sb + SM_EH + (wk * 128 + b_row) * 48 + b_col * 2;

    const float* latb = latent + ((size_t)n * D_ + (size_t)m * DG_) * HW_ + s0;
    const uint4* ebH = (const uint4*)(g_Eh + (size_t)m * K_ * DG_);
    const uint4* vtH = (const uint4*)(g_Vh + (size_t)m * DG_ * K_);

    // ================= GEMM1: logits[64 pix][256 k], cp.async E + ping-pong =================
    float acc[16][4];
#pragma unroll
    for (int i = 0; i < 16; i++)
#pragma unroll
        for (int j = 0; j < 4; j++) acc[i][j] = 0.f;

    float pfA[4];
    LOAD_A(0);
    STS_A(0);
    CP_E(0, 0); CP_COMMIT();
    LOAD_A(1);
    CP_WAIT0();
    __syncthreads();

    for (int c8 = 0; c8 < 8; c8++) {
        const int buf = c8 & 1;
        if (c8 < 7) {
            CP_E(c8 + 1, buf ^ 1); CP_COMMIT();
            STS_A(buf ^ 1);                    // pfA holds chunk c8+1
            if (c8 < 6) LOAD_A(c8 + 2);
        }
        uint32_t ah[4];
        ldsm4(ah, aAh + buf * 3072);
#pragma unroll
        for (int nf2 = 0; nf2 < 8; nf2++) {
            uint32_t bh[4];
            ldsm4(bh, aEh + buf * 12288 + nf2 * 768);
            mma_f16(acc[2 * nf2], ah, bh);
            mma_f16(acc[2 * nf2 + 1], ah, bh + 2);
        }
        if (c8 < 7) CP_WAIT0();
        __syncthreads();
    }

    // ================= Epilogue pass 1: logits out, top-2, e -> acc =================
    const int p_r = wp * 16 + gid;
    const size_t pgA = (size_t)(p0 + p_r), pgB = pgA + 8;
    float* lpA = logit_out + (pgA * M_ + m) * K_ + wk * 128 + 2 * tig;
    float* lpB = logit_out + (pgB * M_ + m) * K_ + wk * 128 + 2 * tig;
    const float* upA = unif + (pgA * M_ + m) * K_ + wk * 128 + 2 * tig;
    const float* upB = unif + (pgB * M_ + m) * K_ + wk * 128 + 2 * tig;

    float b1r[2] = {-3.4e38f, -3.4e38f}, b2r[2] = {-3.4e38f, -3.4e38f};
    int i1r[2] = {0, 0};
    float sumr[2] = {0.f, 0.f};

#pragma unroll
    for (int nf = 0; nf < 16; nf++) {
        int kk = wk * 128 + nf * 8 + 2 * tig;
        float l00 = acc[nf][0], l01 = acc[nf][1], l10 = acc[nf][2], l11 = acc[nf][3];
        *(float2*)(lpA + nf * 8) = make_float2(l00, l01);
        *(float2*)(lpB + nf * 8) = make_float2(l10, l11);
        float2 u0 = *(const float2*)(upA + nf * 8);
        float2 u1 = *(const float2*)(upB + nf * 8);
        UPD(b1r[0], b2r[0], i1r[0], l00, kk);
        UPD(b1r[0], b2r[0], i1r[0], l01, kk + 1);
        UPD(b1r[1], b2r[1], i1r[1], l10, kk);
        UPD(b1r[1], b2r[1], i1r[1], l11, kk + 1);
        float e00 = __fdividef(__expf(l00), neglog_acc(u0.x));
        float e01 = __fdividef(__expf(l01), neglog_acc(u0.y));
        float e10 = __fdividef(__expf(l10), neglog_acc(u1.x));
        float e11 = __fdividef(__expf(l11), neglog_acc(u1.y));
        sumr[0] += e00 + e01;
        sumr[1] += e10 + e11;
        acc[nf][0] = e00; acc[nf][1] = e01; acc[nf][2] = e10; acc[nf][3] = e11;
    }

    // V(0) load: fully async, overlaps the remaining epilogue
    CP_V(0, 0); CP_COMMIT();

#pragma unroll
    for (int r = 0; r < 2; r++) {
#pragma unroll
        for (int o = 1; o <= 2; o <<= 1) {
            float ob1 = __shfl_xor_sync(0xFFFFFFFFu, b1r[r], o);
            int   oi1 = __shfl_xor_sync(0xFFFFFFFFu, i1r[r], o);
            float ob2 = __shfl_xor_sync(0xFFFFFFFFu, b2r[r], o);
            if (ob1 > b1r[r] || (ob1 == b1r[r] && oi1 < i1r[r])) {
                b2r[r] = fmaxf(b1r[r], ob2); b1r[r] = ob1; i1r[r] = oi1;
            } else b2r[r] = fmaxf(b2r[r], ob1);
            sumr[r] += __shfl_xor_sync(0xFFFFFFFFu, sumr[r], o);
        }
    }
    if (tig == 0) {
        b1s[wk * 64 + p_r] = b1r[0];  b1s[wk * 64 + p_r + 8] = b1r[1];
        b2s[wk * 64 + p_r] = b2r[0];  b2s[wk * 64 + p_r + 8] = b2r[1];
        i1s[wk * 64 + p_r] = i1r[0];  i1s[wk * 64 + p_r + 8] = i1r[1];
        sums[wk * 64 + p_r] = sumr[0]; sums[wk * 64 + p_r + 8] = sumr[1];
    }
    __syncthreads();

    if (tid < 64) {
        const int p = tid;
        const size_t pg = (size_t)(p0 + p);
        float a1 = b1s[p], a2 = b2s[p];           int ai = i1s[p];
        float c1 = b1s[64 + p], c2 = b2s[64 + p]; int ci = i1s[64 + p];
        float b1, b2; int i1;
        if (a1 >= c1) { b1 = a1; i1 = ai; b2 = fmaxf(a2, fmaxf(c1, c2)); }
        else          { b1 = c1; i1 = ci; b2 = fmaxf(c2, fmaxf(a1, a2)); }
        rinv[p] = 1.0f / (sums[p] + sums[64 + p]);
        code_out[pg * M_ + m] = (float)i1;
        if (b1 - b2 < GAP_THRESH) {
            int idx = atomicAdd(&g_count, 1);
            if (idx < CAP_) g_list[idx] = (int)(pg * M_ + m);
        }
    }
    __syncthreads();

    // ================= Epilogue pass 2: normalize S -> fp16 smem =================
    {
        const float riA = rinv[p_r], riB = rinv[p_r + 8];
#pragma unroll
        for (int nf = 0; nf < 16; nf++) {
            int kk = wk * 128 + nf * 8 + 2 * tig;
            unsigned short h00 = __half_as_ushort(__float2half_rn(acc[nf][0] * riA));
            unsigned short h01 = __half_as_ushort(__float2half_rn(acc[nf][1] * riA));
            unsigned short h10 = __half_as_ushort(__float2half_rn(acc[nf][2] * riB));
            unsigned short h11 = __half_as_ushort(__float2half_rn(acc[nf][3] * riB));
            *(uint32_t*)(smem + SM_SSH + p_r * 528 + kk * 2)       = ((uint32_t)h01 << 16) | h00;
            *(uint32_t*)(smem + SM_SSH + (p_r + 8) * 528 + kk * 2) = ((uint32_t)h11 << 16) | h10;
        }
    }
    CP_WAIT0();
    __syncthreads();   // publishes S and V0

    // ================= GEMM2: quant[64 pix][128 d], cp.async V ping-pong =================
    float acc2[8][4];
#pragma unroll
    for (int i = 0; i < 8; i++)
#pragma unroll
        for (int j = 0; j < 4; j++) acc2[i][j] = 0.f;

    const uint32_t aSh = sb + SM_SSH + a_row * 528 + a_col * 2;
    const uint32_t bvh = sb + SM_VH + (wk * 64 + b_row) * 80 + b_col * 2;

    for (int it = 0; it < 8; it++) {
        const int buf = it & 1;
        if (it < 7) { CP_V(it + 1, buf ^ 1); CP_COMMIT(); }
#pragma unroll
        for (int s = 0; s < 2; s++) {
            const int k0 = it * 32 + s * 16;
            uint32_t sh[4];
            ldsm4(sh, aSh + k0 * 2);
#pragma unroll
            for (int nf2 = 0; nf2 < 4; nf2++) {
                uint32_t bh[4];
                ldsm4(bh, bvh + buf * 10240 + nf2 * 1280 + s * 32);
                mma_f16(acc2[2 * nf2], sh, bh);
                mma_f16(acc2[2 * nf2 + 1], sh, bh + 2);
            }
        }
        if (it < 7) CP_WAIT0();
        __syncthreads();
    }

#pragma unroll
    for (int nf = 0; nf < 8; nf++) {
        int d = wk * 64 + 8 * nf + 2 * tig;
        qbuf[p_r * 132 + d]       = acc2[nf][0];
        qbuf[p_r * 132 + d + 1]   = acc2[nf][1];
        qbuf[(p_r + 8) * 132 + d]     = acc2[nf][2];
        qbuf[(p_r + 8) * 132 + d + 1] = acc2[nf][3];
    }
    __syncthreads();
    {
        const int pix = tid & 63, dg2 = tid >> 6;
        float* qb = quant_out + ((size_t)n * D_ + (size_t)m * DG_) * HW_ + s0 + pix;
#pragma unroll
        for (int j = 0; j < 32; j++) {
            int d = dg2 * 32 + j;
            qb[(size_t)d * HW_] = qbuf[pix * 132 + d];
        }
    }
}

// ---------------- refine: dd-exact argmax for near-tie pixels ----------------
__global__ void __launch_bounds__(128)
refine_kernel(const float* __restrict__ latent, const float* __restrict__ wq,
              const float* __restrict__ logit_out, float* __restrict__ code_out) {
    __shared__ float qv_s[4][DG_], qh_s[4][DG_], ql_s[4][DG_];
    const int wid = threadIdx.x >> 5, lane = threadIdx.x & 31;
    const int gw = blockIdx.x * 4 + wid, tw = gridDim.x * 4;
    int cnt = g_count; if (cnt > CAP_) cnt = CAP_;
    for (int e = gw; e < cnt; e += tw) {
        int ent = g_list[e], m = ent & 7, pg = ent >> 3;
        int n = pg >> 10, s = pg & 1023;
        const float* latb = latent + ((size_t)n * D_ + (size_t)m * DG_) * HW_ + s;
        for (int d = lane; d < DG_; d += 32) qv_s[wid][d] = latb[(size_t)d * HW_];
        __syncwarp();
        const float* wqm = wq + (size_t)m * DG_ * DG_;
#pragma unroll
        for (int ci = 0; ci < 4; ci++) {
            int c = lane + 32 * ci;
            const float* wr = wqm + (size_t)c * DG_;
            dd a; a.h = a.l = 0.f;
            for (int d = 0; d < DG_; d++) a = dd_fma(a, qv_s[wid][d], wr[d]);
            qh_s[wid][c] = a.h; ql_s[wid][c] = a.l;
        }
        __syncwarp();
        const float* lo = logit_out + ((size_t)pg * M_ + m) * K_;
        float l[8], fm = -3.4e38f;
#pragma unroll
        for (int j = 0; j < 8; j++) { l[j] = lo[lane * 8 + j]; fm = fmaxf(fm, l[j]); }
#pragma unroll
        for (int o = 16; o > 0; o >>= 1) fm = fmaxf(fm, __shfl_xor_sync(0xFFFFFFFFu, fm, o));
        float thresh = fm - REF_WIN;
        double bestv = -1e300; int besti = 1 << 30;
        const float* kph = g_KPH + ((size_t)m * K_) * DG_;
        const float* kpl = g_KPL + ((size_t)m * K_) * DG_;
#pragma unroll
        for (int j = 0; j < 8; j++) {
            unsigned b = __ballot_sync(0xFFFFFFFFu, l[j] >= thresh);
            while (b) {
                int src = __ffs(b) - 1; b &= b - 1;
                int k = src * 8 + j;
                const float* kh = kph + (size_t)k * DG_;
                const float* kl = kpl + (size_t)k * DG_;
                dd a; a.h = a.l = 0.f;
#pragma unroll
                for (int ci = 0; ci < 4; ci++) {
                    int c = lane + 32 * ci;
                    dd kp; kp.h = kh[c]; kp.l = kl[c];
                    dd qp; qp.h = qh_s[wid][c]; qp.l = ql_s[wid][c];
                    a = dd_add(a, dd_mul(kp, qp));
                }
                double v = (double)a.h + (double)a.l;
#pragma unroll
                for (int o = 16; o > 0; o >>= 1) v += __shfl_xor_sync(0xFFFFFFFFu, v, o);
                if (v > bestv || (v == bestv && k < besti)) { bestv = v; besti = k; }
            }
        }
        if (lane == 0) code_out[(size_t)pg * M_ + m] = (float)besti;
    }
}

extern "C" void kernel_launch(void* const* d_in, const int* in_sizes, int n_in,
                              void* d_out, int out_size) {
    const float* latent   = (const float*)d_in[0];
    const float* codebook = (const float*)d_in[1];
    const float* wq       = (const float*)d_in[2];
    const float* wk       = (const float*)d_in[3];
    const float* wv       = (const float*)d_in[4];
    const float* unif     = (const float*)d_in[5];
    float* out   = (float*)d_out;
    float* quant = out;
    float* code  = out + QUANT_ELEMS;
    float* logit = out + QUANT_ELEMS + CODE_ELEMS;

    precompute_kernel<<<dim3(K_ / 4, M_), 256>>>(codebook, wq, wk, wv);
    cudaFuncSetAttribute(main_kernel, cudaFuncAttributeMaxDynamicSharedMemorySize, SMEM_TOTAL);
    main_kernel<<<dim3(NPIX_ / 64, M_), 256, SMEM_TOTAL>>>(latent, unif, quant, code, logit);
    refine_kernel<<<256, 128>>>(latent, wq, logit, code);
}

// round 15
// speedup vs baseline: 1.1887x; 1.0272x over previous
#include <cuda_runtime.h>
#include <cuda_fp16.h>
#include <cstdint>

#define M_    8
#define K_    256
#define DG_   128
#define D_    1024
#define HW_   1024
#define NPIX_ 32768
#define QUANT_ELEMS 33554432
#define CODE_ELEMS  262144
#define GAP_THRESH 5e-3f
#define REF_WIN    8e-3f
#define CAP_       32768

__device__ unsigned short g_Eh[M_ * K_ * DG_];   // E [m][k][d] fp16
__device__ unsigned short g_Vh[M_ * DG_ * K_];   // Vt [m][d][k] fp16
__device__ float g_KPH[M_ * K_ * DG_];
__device__ float g_KPL[M_ * K_ * DG_];
__device__ int   g_count;
__device__ int   g_list[CAP_];

__device__ __forceinline__ uint32_t smem_to_u32(const void* p) {
    uint32_t a;
    asm("{ .reg .u64 t; cvta.to.shared.u64 t, %1; cvt.u32.u64 %0, t; }" : "=r"(a) : "l"(p));
    return a;
}
__device__ __forceinline__ void ldsm4(uint32_t* r, uint32_t addr) {
    asm volatile("ldmatrix.sync.aligned.m8n8.x4.shared.b16 {%0,%1,%2,%3}, [%4];"
        : "=r"(r[0]), "=r"(r[1]), "=r"(r[2]), "=r"(r[3]) : "r"(addr));
}
__device__ __forceinline__ void mma_f16(float* d, const uint32_t* a, const uint32_t* b) {
    asm volatile("mma.sync.aligned.m16n8k16.row.col.f32.f16.f16.f32 "
        "{%0,%1,%2,%3}, {%4,%5,%6,%7}, {%8,%9}, {%0,%1,%2,%3};"
        : "+f"(d[0]), "+f"(d[1]), "+f"(d[2]), "+f"(d[3])
        : "r"(a[0]), "r"(a[1]), "r"(a[2]), "r"(a[3]), "r"(b[0]), "r"(b[1]));
}
#define CP16(dst, src) \
    asm volatile("cp.async.cg.shared.global [%0], [%1], 16;" :: "r"(dst), "l"(src) : "memory")
#define CP_COMMIT() asm volatile("cp.async.commit_group;" ::: "memory")
#define CP_WAIT0()  asm volatile("cp.async.wait_group 0;" ::: "memory")
#define CP_WAIT1()  asm volatile("cp.async.wait_group 1;" ::: "memory")

struct dd { float h, l; };
__device__ __forceinline__ dd two_sum(float a, float b) {
    float s = __fadd_rn(a, b), bb = __fsub_rn(s, a);
    float e = __fadd_rn(__fsub_rn(a, __fsub_rn(s, bb)), __fsub_rn(b, bb));
    dd r; r.h = s; r.l = e; return r;
}
__device__ __forceinline__ dd two_prod(float a, float b) {
    float p = __fmul_rn(a, b), e = __fmaf_rn(a, b, -p);
    dd r; r.h = p; r.l = e; return r;
}
__device__ __forceinline__ dd dd_add(dd x, dd y) {
    dd s = two_sum(x.h, y.h);
    float lo = __fadd_rn(__fadd_rn(x.l, y.l), s.l);
    float hi = __fadd_rn(s.h, lo);
    float l = __fadd_rn(__fsub_rn(s.h, hi), lo);
    dd r; r.h = hi; r.l = l; return r;
}
__device__ __forceinline__ dd dd_fma(dd a, float x, float y) { return dd_add(a, two_prod(x, y)); }
__device__ __forceinline__ dd dd_mul(dd x, dd y) {
    dd p = two_prod(x.h, y.h);
    float t = __fmaf_rn(x.h, y.l, p.l); t = __fmaf_rn(x.l, y.h, t);
    float hi = __fadd_rn(p.h, t), l = __fadd_rn(__fsub_rn(p.h, hi), t);
    dd r; r.h = hi; r.l = l; return r;
}
__device__ __forceinline__ float neglog_acc(float u) {
    float t = __fsub_rn(u, 1.0f);
    float p = fmaf(t, 0.142857143f, -0.166666667f);
    p = fmaf(t, p, 0.2f); p = fmaf(t, p, -0.25f);
    p = fmaf(t, p, 0.333333333f); p = fmaf(t, p, -0.5f); p = fmaf(t, p, 1.0f);
    return (u > 0.75f) ? -(t * p) : -__logf(u);
}

// ---------------- precompute: kproj(dd), Vt/E fp16 ----------------
#define P_CB 0
#define P_KP 512
#define P_WK 1024
#define P_WV (1024 + 4224)
#define P_WQ 1024
#define P_FLOATS (1024 + 4224 + 4224)

__global__ void __launch_bounds__(256)
precompute_kernel(const float* __restrict__ codebook, const float* __restrict__ wq,
                  const float* __restrict__ wk, const float* __restrict__ wv) {
    __shared__ float sm[P_FLOATS];
    float *cbs = sm + P_CB, *kps = sm + P_KP, *wks = sm + P_WK, *wvs = sm + P_WV, *wqs = sm + P_WQ;
    const int m = blockIdx.y, k0 = blockIdx.x * 4, tid = threadIdx.x;
    const int c = tid & 127, khalf = tid >> 7;
    if (m == 0 && blockIdx.x == 0 && tid == 0) g_count = 0;
#pragma unroll
    for (int r = 0; r < 2; r++) {
        int idx = tid + 256 * r;
        cbs[idx] = codebook[((size_t)m * K_ + k0) * DG_ + idx];
    }
    dd sk[2]; float sv[2];
#pragma unroll
    for (int i = 0; i < 2; i++) { sk[i].h = sk[i].l = 0.f; sv[i] = 0.f; }
    const float* wkm = wk + (size_t)m * DG_ * DG_;
    const float* wvm = wv + (size_t)m * DG_ * DG_;
    for (int dc = 0; dc < DG_; dc += 32) {
        __syncthreads();
#pragma unroll
        for (int r = 0; r < 16; r++) {
            int idx = tid + 256 * r, cc = idx >> 5, j = idx & 31;
            wks[cc * 33 + j] = wkm[(size_t)cc * DG_ + dc + j];
            wvs[cc * 33 + j] = wvm[(size_t)cc * DG_ + dc + j];
        }
        __syncthreads();
#pragma unroll 4
        for (int j = 0; j < 32; j++) {
            float wkv = wks[c * 33 + j], wvv = wvs[c * 33 + j];
#pragma unroll
            for (int i = 0; i < 2; i++) {
                float cbv = cbs[(khalf * 2 + i) * DG_ + dc + j];
                sk[i] = dd_fma(sk[i], cbv, wkv);
                sv[i] = fmaf(cbv, wvv, sv[i]);
            }
        }
    }
#pragma unroll
    for (int i = 0; i < 2; i++) {
        int kk = k0 + khalf * 2 + i;
        size_t gb = ((size_t)m * K_ + kk) * DG_ + c;
        g_KPH[gb] = sk[i].h; g_KPL[gb] = sk[i].l;
        g_Vh[((size_t)m * DG_ + c) * K_ + kk] = __half_as_ushort(__float2half_rn(sv[i]));
        kps[(khalf * 2 + i) * DG_ + c] = sk[i].h;
    }
    const int d = c;
    float ea[2] = {0.f, 0.f};
    const float* wqm = wq + (size_t)m * DG_ * DG_;
    for (int c0 = 0; c0 < DG_; c0 += 32) {
        __syncthreads();
#pragma unroll
        for (int r = 0; r < 16; r++) {
            int idx = tid + 256 * r;
            wqs[idx] = wqm[(size_t)c0 * DG_ + idx];
        }
        __syncthreads();
#pragma unroll 4
        for (int cc = 0; cc < 32; cc++) {
            float wv_ = wqs[cc * DG_ + d];
#pragma unroll
            for (int i = 0; i < 2; i++)
                ea[i] = fmaf(kps[(khalf * 2 + i) * DG_ + c0 + cc], wv_, ea[i]);
        }
    }
#pragma unroll
    for (int i = 0; i < 2; i++)
        g_Eh[((size_t)m * K_ + k0 + khalf * 2 + i) * DG_ + d] =
            __half_as_ushort(__float2half_rn(ea[i]));
}

// ---------------- main mma.sync kernel: 64 pix x fixed m, 2 CTAs/SM ----------------
// smem map (bytes):
//  [0..4096)         small buffers
//  [4096..37888)     S (normalized) fp16 [64][528B rows]
//  [37888..83968)    stage: A0..A2 (3x3072=9216) + E0..E2 (3x12288=36864) = 46080
//                     / V0..V2 (3x10240=30720) / qbuf[64][132]f32 = 33792
#define SM_B1S  0
#define SM_B2S  512
#define SM_I1S  1024
#define SM_SUMS 1536
#define SM_RI   2048
#define SM_SSH  4096
#define SM_STG  37888
#define SM_AH   (SM_STG)
#define SM_EH   (SM_STG + 9216)
#define SM_VH   (SM_STG)
#define SM_QB   (SM_STG)
#define SMEM_TOTAL (37888 + 46080)   // 83968

#define UPD(b1, b2, i1, v, k) do { \
    if ((v) > (b1)) { b2 = b1; b1 = (v); i1 = (k); } \
    else if ((v) > (b2)) b2 = (v); } while (0)

#define LOAD_A(c8) do { _Pragma("unroll") \
    for (int j = 0; j < 2; j++) { \
        int dp = (tid >> 6) + 4 * j, pix = tid & 63; \
        pfA[2 * j]     = latb[(size_t)(16 * (c8) + 2 * dp) * HW_ + pix]; \
        pfA[2 * j + 1] = latb[(size_t)(16 * (c8) + 2 * dp + 1) * HW_ + pix]; \
    } } while (0)
#define STS_A(buf) do { char* ab = smem + SM_AH + (buf) * 3072; _Pragma("unroll") \
    for (int j = 0; j < 2; j++) { \
        int dp = (tid >> 6) + 4 * j, pix = tid & 63; \
        unsigned short h0 = __half_as_ushort(__float2half_rn(pfA[2 * j])); \
        unsigned short h1 = __half_as_ushort(__float2half_rn(pfA[2 * j + 1])); \
        *(uint32_t*)(ab + pix * 48 + dp * 4) = ((uint32_t)h1 << 16) | h0; \
    } } while (0)
#define CP_E(c8, buf) do { uint32_t eb = sb + SM_EH + (buf) * 12288; _Pragma("unroll") \
    for (int j = 0; j < 2; j++) \
        CP16(eb + tid * 48 + j * 16, ebH + (size_t)tid * 16 + (c8) * 2 + j); \
    } while (0)
#define CP_V(it, buf) do { uint32_t vb = sb + SM_VH + (buf) * 10240; _Pragma("unroll") \
    for (int jj = 0; jj < 2; jj++) { \
        int q = tid + 256 * jj; \
        CP16(vb + (q >> 2) * 80 + (q & 3) * 16, vtH + (size_t)(q >> 2) * 32 + (it) * 4 + (q & 3)); \
    } } while (0)

__global__ void __launch_bounds__(256, 2)
main_kernel(const float* __restrict__ latent, const float* __restrict__ unif,
            float* __restrict__ quant_out, float* __restrict__ code_out,
            float* __restrict__ logit_out) {
    extern __shared__ char smem[];
    const uint32_t sb = smem_to_u32(smem);
    const int m = blockIdx.y, p0 = blockIdx.x * 64;
    const int n = p0 >> 10, s0 = p0 & 1023;
    const int tid = threadIdx.x, w = tid >> 5, lane = tid & 31;
    const int wp = w >> 1, wk = w & 1;
    const int gid = lane >> 2, tig = lane & 3;
    const int li = lane & 7, lg = lane >> 3;

    float* b1s = (float*)(smem + SM_B1S);
    float* b2s = (float*)(smem + SM_B2S);
    int*   i1s = (int*)(smem + SM_I1S);
    float* sums = (float*)(smem + SM_SUMS);
    float* rinv = (float*)(smem + SM_RI);
    float* qbuf = (float*)(smem + SM_QB);

    const int a_row = wp * 16 + ((lg & 1) << 3) + li;
    const int a_col = ((lg >> 1) << 3);
    const int b_row = ((lg >> 1) << 3) + li;
    const int b_col = ((lg & 1) << 3);
    const uint32_t aAh = sb + SM_AH + a_row * 48 + a_col * 2;
    const uint32_t aEh = sb + SM_EH + (wk * 128 + b_row) * 48 + b_col * 2;

    const float* latb = latent + ((size_t)n * D_ + (size_t)m * DG_) * HW_ + s0;
    const uint4* ebH = (const uint4*)(g_Eh + (size_t)m * K_ * DG_);
    const uint4* vtH = (const uint4*)(g_Vh + (size_t)m * DG_ * K_);

    // ================= GEMM1: logits[64 pix][256 k], depth-3 cp.async =================
    float acc[16][4];
#pragma unroll
    for (int i = 0; i < 16; i++)
#pragma unroll
        for (int j = 0; j < 4; j++) acc[i][j] = 0.f;

    float pfA[4];
    LOAD_A(0);
    CP_E(0, 0); CP_COMMIT();
    CP_E(1, 1); CP_COMMIT();
    STS_A(0);
    LOAD_A(1);
    CP_WAIT1();          // E0 landed (E1 may still be in flight)
    __syncthreads();

    for (int c8 = 0; c8 < 8; c8++) {
        const int buf = c8 % 3;
        if (c8 < 6) { CP_E(c8 + 2, (c8 + 2) % 3); CP_COMMIT(); }
        if (c8 < 7) {
            STS_A((c8 + 1) % 3);      // pfA holds chunk c8+1
            if (c8 < 6) LOAD_A(c8 + 2);
        }
        uint32_t ah[4];
        ldsm4(ah, aAh + buf * 3072);
#pragma unroll
        for (int nf2 = 0; nf2 < 8; nf2++) {
            uint32_t bh[4];
            ldsm4(bh, aEh + buf * 12288 + nf2 * 768);
            mma_f16(acc[2 * nf2], ah, bh);
            mma_f16(acc[2 * nf2 + 1], ah, bh + 2);
        }
        if (c8 < 6) CP_WAIT1(); else CP_WAIT0();
        __syncthreads();
    }

    // ================= Epilogue pass 1: logits out, top-2, e -> acc =================
    const int p_r = wp * 16 + gid;
    const size_t pgA = (size_t)(p0 + p_r), pgB = pgA + 8;
    float* lpA = logit_out + (pgA * M_ + m) * K_ + wk * 128 + 2 * tig;
    float* lpB = logit_out + (pgB * M_ + m) * K_ + wk * 128 + 2 * tig;
    const float* upA = unif + (pgA * M_ + m) * K_ + wk * 128 + 2 * tig;
    const float* upB = unif + (pgB * M_ + m) * K_ + wk * 128 + 2 * tig;

    float b1r[2] = {-3.4e38f, -3.4e38f}, b2r[2] = {-3.4e38f, -3.4e38f};
    int i1r[2] = {0, 0};
    float sumr[2] = {0.f, 0.f};

#pragma unroll
    for (int nf = 0; nf < 16; nf++) {
        int kk = wk * 128 + nf * 8 + 2 * tig;
        float l00 = acc[nf][0], l01 = acc[nf][1], l10 = acc[nf][2], l11 = acc[nf][3];
        *(float2*)(lpA + nf * 8) = make_float2(l00, l01);
        *(float2*)(lpB + nf * 8) = make_float2(l10, l11);
        float2 u0 = *(const float2*)(upA + nf * 8);
        float2 u1 = *(const float2*)(upB + nf * 8);
        UPD(b1r[0], b2r[0], i1r[0], l00, kk);
        UPD(b1r[0], b2r[0], i1r[0], l01, kk + 1);
        UPD(b1r[1], b2r[1], i1r[1], l10, kk);
        UPD(b1r[1], b2r[1], i1r[1], l11, kk + 1);
        float e00 = __fdividef(__expf(l00), neglog_acc(u0.x));
        float e01 = __fdividef(__expf(l01), neglog_acc(u0.y));
        float e10 = __fdividef(__expf(l10), neglog_acc(u1.x));
        float e11 = __fdividef(__expf(l11), neglog_acc(u1.y));
        sumr[0] += e00 + e01;
        sumr[1] += e10 + e11;
        acc[nf][0] = e00; acc[nf][1] = e01; acc[nf][2] = e10; acc[nf][3] = e11;
    }

    // V0, V1: fully async, overlap the remaining epilogue (2 groups in flight)
    CP_V(0, 0); CP_COMMIT();
    CP_V(1, 1); CP_COMMIT();

#pragma unroll
    for (int r = 0; r < 2; r++) {
#pragma unroll
        for (int o = 1; o <= 2; o <<= 1) {
            float ob1 = __shfl_xor_sync(0xFFFFFFFFu, b1r[r], o);
            int   oi1 = __shfl_xor_sync(0xFFFFFFFFu, i1r[r], o);
            float ob2 = __shfl_xor_sync(0xFFFFFFFFu, b2r[r], o);
            if (ob1 > b1r[r] || (ob1 == b1r[r] && oi1 < i1r[r])) {
                b2r[r] = fmaxf(b1r[r], ob2); b1r[r] = ob1; i1r[r] = oi1;
            } else b2r[r] = fmaxf(b2r[r], ob1);
            sumr[r] += __shfl_xor_sync(0xFFFFFFFFu, sumr[r], o);
        }
    }
    if (tig == 0) {
        b1s[wk * 64 + p_r] = b1r[0];  b1s[wk * 64 + p_r + 8] = b1r[1];
        b2s[wk * 64 + p_r] = b2r[0];  b2s[wk * 64 + p_r + 8] = b2r[1];
        i1s[wk * 64 + p_r] = i1r[0];  i1s[wk * 64 + p_r + 8] = i1r[1];
        sums[wk * 64 + p_r] = sumr[0]; sums[wk * 64 + p_r + 8] = sumr[1];
    }
    __syncthreads();

    if (tid < 64) {
        const int p = tid;
        const size_t pg = (size_t)(p0 + p);
        float a1 = b1s[p], a2 = b2s[p];           int ai = i1s[p];
        float c1 = b1s[64 + p], c2 = b2s[64 + p]; int ci = i1s[64 + p];
        float b1, b2; int i1;
        if (a1 >= c1) { b1 = a1; i1 = ai; b2 = fmaxf(a2, fmaxf(c1, c2)); }
        else          { b1 = c1; i1 = ci; b2 = fmaxf(c2, fmaxf(a1, a2)); }
        rinv[p] = 1.0f / (sums[p] + sums[64 + p]);
        code_out[pg * M_ + m] = (float)i1;
        if (b1 - b2 < GAP_THRESH) {
            int idx = atomicAdd(&g_count, 1);
            if (idx < CAP_) g_list[idx] = (int)(pg * M_ + m);
        }
    }
    __syncthreads();

    // ================= Epilogue pass 2: normalize S -> fp16 smem =================
    {
        const float riA = rinv[p_r], riB = rinv[p_r + 8];
#pragma unroll
        for (int nf = 0; nf < 16; nf++) {
            int kk = wk * 128 + nf * 8 + 2 * tig;
            unsigned short h00 = __half_as_ushort(__float2half_rn(acc[nf][0] * riA));
            unsigned short h01 = __half_as_ushort(__float2half_rn(acc[nf][1] * riA));
            unsigned short h10 = __half_as_ushort(__float2half_rn(acc[nf][2] * riB));
            unsigned short h11 = __half_as_ushort(__float2half_rn(acc[nf][3] * riB));
            *(uint32_t*)(smem + SM_SSH + p_r * 528 + kk * 2)       = ((uint32_t)h01 << 16) | h00;
            *(uint32_t*)(smem + SM_SSH + (p_r + 8) * 528 + kk * 2) = ((uint32_t)h11 << 16) | h10;
        }
    }
    CP_WAIT1();          // V0 landed (V1 may still be in flight)
    __syncthreads();     // publishes S and V0

    // ================= GEMM2: quant[64 pix][128 d], depth-3 cp.async V =================
    float acc2[8][4];
#pragma unroll
    for (int i = 0; i < 8; i++)
#pragma unroll
        for (int j = 0; j < 4; j++) acc2[i][j] = 0.f;

    const uint32_t aSh = sb + SM_SSH + a_row * 528 + a_col * 2;
    const uint32_t bvh = sb + SM_VH + (wk * 64 + b_row) * 80 + b_col * 2;

    for (int it = 0; it < 8; it++) {
        const int buf = it % 3;
        if (it < 6) { CP_V(it + 2, (it + 2) % 3); CP_COMMIT(); }
#pragma unroll
        for (int s = 0; s < 2; s++) {
            const int k0 = it * 32 + s * 16;
            uint32_t sh[4];
            ldsm4(sh, aSh + k0 * 2);
#pragma unroll
            for (int nf2 = 0; nf2 < 4; nf2++) {
                uint32_t bh[4];
                ldsm4(bh, bvh + buf * 10240 + nf2 * 1280 + s * 32);
                mma_f16(acc2[2 * nf2], sh, bh);
                mma_f16(acc2[2 * nf2 + 1], sh, bh + 2);
            }
        }
        if (it < 6) CP_WAIT1(); else CP_WAIT0();
        __syncthreads();
    }

#pragma unroll
    for (int nf = 0; nf < 8; nf++) {
        int d = wk * 64 + 8 * nf + 2 * tig;
        qbuf[p_r * 132 + d]       = acc2[nf][0];
        qbuf[p_r * 132 + d + 1]   = acc2[nf][1];
        qbuf[(p_r + 8) * 132 + d]     = acc2[nf][2];
        qbuf[(p_r + 8) * 132 + d + 1] = acc2[nf][3];
    }
    __syncthreads();
    {
        const int pix = tid & 63, dg2 = tid >> 6;
        float* qb = quant_out + ((size_t)n * D_ + (size_t)m * DG_) * HW_ + s0 + pix;
#pragma unroll
        for (int j = 0; j < 32; j++) {
            int d = dg2 * 32 + j;
            qb[(size_t)d * HW_] = qbuf[pix * 132 + d];
        }
    }
}

// ---------------- refine: dd-exact argmax for near-tie pixels ----------------
__global__ void __launch_bounds__(128)
refine_kernel(const float* __restrict__ latent, const float* __restrict__ wq,
              const float* __restrict__ logit_out, float* __restrict__ code_out) {
    __shared__ float qv_s[4][DG_], qh_s[4][DG_], ql_s[4][DG_];
    const int wid = threadIdx.x >> 5, lane = threadIdx.x & 31;
    const int gw = blockIdx.x * 4 + wid, tw = gridDim.x * 4;
    int cnt = g_count; if (cnt > CAP_) cnt = CAP_;
    for (int e = gw; e < cnt; e += tw) {
        int ent = g_list[e], m = ent & 7, pg = ent >> 3;
        int n = pg >> 10, s = pg & 1023;
        const float* latb = latent + ((size_t)n * D_ + (size_t)m * DG_) * HW_ + s;
        for (int d = lane; d < DG_; d += 32) qv_s[wid][d] = latb[(size_t)d * HW_];
        __syncwarp();
        const float* wqm = wq + (size_t)m * DG_ * DG_;
#pragma unroll
        for (int ci = 0; ci < 4; ci++) {
            int c = lane + 32 * ci;
            const float* wr = wqm + (size_t)c * DG_;
            dd a; a.h = a.l = 0.f;
            for (int d = 0; d < DG_; d++) a = dd_fma(a, qv_s[wid][d], wr[d]);
            qh_s[wid][c] = a.h; ql_s[wid][c] = a.l;
        }
        __syncwarp();
        const float* lo = logit_out + ((size_t)pg * M_ + m) * K_;
        float l[8], fm = -3.4e38f;
#pragma unroll
        for (int j = 0; j < 8; j++) { l[j] = lo[lane * 8 + j]; fm = fmaxf(fm, l[j]); }
#pragma unroll
        for (int o = 16; o > 0; o >>= 1) fm = fmaxf(fm, __shfl_xor_sync(0xFFFFFFFFu, fm, o));
        float thresh = fm - REF_WIN;
        double bestv = -1e300; int besti = 1 << 30;
        const float* kph = g_KPH + ((size_t)m * K_) * DG_;
        const float* kpl = g_KPL + ((size_t)m * K_) * DG_;
#pragma unroll
        for (int j = 0; j < 8; j++) {
            unsigned b = __ballot_sync(0xFFFFFFFFu, l[j] >= thresh);
            while (b) {
                int src = __ffs(b) - 1; b &= b - 1;
                int k = src * 8 + j;
                const float* kh = kph + (size_t)k * DG_;
                const float* kl = kpl + (size_t)k * DG_;
                dd a; a.h = a.l = 0.f;
#pragma unroll
                for (int ci = 0; ci < 4; ci++) {
                    int c = lane + 32 * ci;
                    dd kp; kp.h = kh[c]; kp.l = kl[c];
                    dd qp; qp.h = qh_s[wid][c]; qp.l = ql_s[wid][c];
                    a = dd_add(a, dd_mul(kp, qp));
                }
                double v = (double)a.h + (double)a.l;
#pragma unroll
                for (int o = 16; o > 0; o >>= 1) v += __shfl_xor_sync(0xFFFFFFFFu, v, o);
                if (v > bestv || (v == bestv && k < besti)) { bestv = v; besti = k; }
            }
        }
        if (lane == 0) code_out[(size_t)pg * M_ + m] = (float)besti;
    }
}

extern "C" void kernel_launch(void* const* d_in, const int* in_sizes, int n_in,
                              void* d_out, int out_size) {
    const float* latent   = (const float*)d_in[0];
    const float* codebook = (const float*)d_in[1];
    const float* wq       = (const float*)d_in[2];
    const float* wk       = (const float*)d_in[3];
    const float* wv       = (const float*)d_in[4];
    const float* unif     = (const float*)d_in[5];
    float* out   = (float*)d_out;
    float* quant = out;
    float* code  = out + QUANT_ELEMS;
    float* logit = out + QUANT_ELEMS + CODE_ELEMS;

    precompute_kernel<<<dim3(K_ / 4, M_), 256>>>(codebook, wq, wk, wv);
    cudaFuncSetAttribute(main_kernel, cudaFuncAttributeMaxDynamicSharedMemorySize, SMEM_TOTAL);
    main_kernel<<<dim3(NPIX_ / 64, M_), 256, SMEM_TOTAL>>>(latent, unif, quant, code, logit);
    refine_kernel<<<256, 128>>>(latent, wq, logit, code);
}